// round 5
// baseline (speedup 1.0000x reference)
#include <cuda_runtime.h>
#include <math.h>
#include <stdint.h>

// Problem constants
#define B_  4096
#define S_  23
#define D_  768
#define H_  8
#define HD_ 96
#define L_  50
#define C_  184      // H_*S_ score columns
#define CP_ 192      // padded score columns
#define UD_ 6912     // 9*D_ : [cls_sum | u_0..u_7]

// ---------------- scratch (device globals; 16B-aligned for float4 access) ----
__device__ __align__(16) float g_qmiss[S_ * D_];
__device__ __align__(16) float g_P[CP_ * D_];
__device__ __align__(16) float g_qb[C_];
__device__ __align__(16) float g_Wcp[L_ * D_];
__device__ __align__(16) float g_Wbig[(size_t)L_ * UD_];
__device__ __align__(16) float g_cbias[L_ + 2];
__device__ __align__(16) float g_logit_mt[L_ + 2];
__device__ __align__(16) float g_mtsum[D_];
__device__ __align__(16) int   g_nexist[B_];
__device__ __align__(16) int   g_start[B_ + 4];
__device__ __align__(16) int   g_rowidx[B_ * S_];
__device__ __align__(16) float g_Y[(size_t)B_ * S_ * CP_];
__device__ __align__(16) float g_U[(size_t)B_ * UD_];

// ---------------- precompute kernels ----------------------------------------

// qmiss[q,:] = missing_table[q,:] @ Wq^T + bq
__global__ void k_qmiss(const float* __restrict__ mt, const float* __restrict__ ipw,
                        const float* __restrict__ ipb) {
    __shared__ float row[D_];
    int q = blockIdx.x;
    for (int i = threadIdx.x; i < D_; i += blockDim.x) row[i] = mt[q * D_ + i];
    __syncthreads();
    for (int o = threadIdx.x; o < D_; o += blockDim.x) {
        const float* w = ipw + (size_t)o * D_;
        float acc = ipb[o];
        #pragma unroll 4
        for (int d = 0; d < D_; d++) acc += row[d] * w[d];
        g_qmiss[q * D_ + o] = acc;
    }
}

// P[c=h*S+q, d] = sum_j qmiss[q, h*96+j] * Wk[h*96+j, d];  qb[c] = qmiss_h . bk_h
__global__ void k_P(const float* __restrict__ ipw, const float* __restrict__ ipb) {
    int c = blockIdx.y;
    int h = c / S_, q = c % S_;
    __shared__ float qr[HD_];
    if (threadIdx.x < HD_) qr[threadIdx.x] = g_qmiss[q * D_ + h * HD_ + threadIdx.x];
    __syncthreads();
    int d = blockIdx.x * blockDim.x + threadIdx.x;
    const float* wk = ipw + (size_t)D_ * D_;
    float acc = 0.f;
    #pragma unroll 8
    for (int j = 0; j < HD_; j++) acc += qr[j] * wk[(size_t)(h * HD_ + j) * D_ + d];
    g_P[(size_t)c * D_ + d] = acc;
    if (blockIdx.x == 0 && threadIdx.x == 0) {
        const float* bk = ipb + D_;
        float s = 0.f;
        for (int j = 0; j < HD_; j++) s += qr[j] * bk[h * HD_ + j];
        g_qb[c] = s;
    }
}

// zero the padding rows of P so vector loads read defined data
__global__ void k_Ppad() {
    int i = blockIdx.x * blockDim.x + threadIdx.x;
    if (i < (CP_ - C_) * D_) g_P[(size_t)C_ * D_ + i] = 0.f;
}

// Wcp[l,:] = pred_w[l,:] @ out_proj_w
__global__ void k_wcp(const float* __restrict__ predw, const float* __restrict__ outw) {
    int l = blockIdx.y;
    __shared__ float pr[D_];
    for (int i = threadIdx.x; i < D_; i += blockDim.x) pr[i] = predw[l * D_ + i];
    __syncthreads();
    int d = blockIdx.x * blockDim.x + threadIdx.x;
    float acc = 0.f;
    #pragma unroll 4
    for (int m = 0; m < D_; m++) acc += pr[m] * outw[(size_t)m * D_ + d];
    g_Wcp[l * D_ + d] = acc;
}

// Wbig[l, 0:768] = pred_w[l,:]/S ; Wbig[l, 768+h*768+d] = (sum_j Wcp[l,h96+j]*Wv[h96+j,d])/S
__global__ void k_wbig(const float* __restrict__ predw, const float* __restrict__ ipw) {
    int l = blockIdx.y;
    __shared__ float wc[D_];
    for (int i = threadIdx.x; i < D_; i += blockDim.x) wc[i] = g_Wcp[l * D_ + i];
    __syncthreads();
    int col = blockIdx.x * blockDim.x + threadIdx.x;
    const float inv = 1.f / (float)S_;
    float v;
    if (col < D_) {
        v = predw[l * D_ + col];
    } else {
        int h = (col - D_) / D_, d = (col - D_) % D_;
        const float* wv = ipw + (size_t)2 * D_ * D_;
        float acc = 0.f;
        #pragma unroll 8
        for (int j = 0; j < HD_; j++) acc += wc[h * HD_ + j] * wv[(size_t)(h * HD_ + j) * D_ + d];
        v = acc;
    }
    g_Wbig[(size_t)l * UD_ + col] = v * inv;
}

__global__ void k_mtsum(const float* __restrict__ mt) {
    int d = threadIdx.x;
    float s = 0.f;
    for (int q = 0; q < S_; q++) s += mt[q * D_ + d];
    g_mtsum[d] = s;
}

// cbias[l] = (bv.Wcp[l] + b_out.pred_w[l]) / S ; logit_mt[l] = mt_sum.pred_w[l]/S + pred_b[l]
__global__ void k_lvec(const float* __restrict__ predw, const float* __restrict__ predb,
                       const float* __restrict__ ipb, const float* __restrict__ outb) {
    int l = threadIdx.x;
    if (l >= L_) return;
    const float inv = 1.f / (float)S_;
    const float* bv = ipb + 2 * D_;
    float cb = 0.f;
    for (int i = 0; i < D_; i++) cb += bv[i] * g_Wcp[l * D_ + i];
    for (int m = 0; m < D_; m++) cb += outb[m] * predw[l * D_ + m];
    g_cbias[l] = cb * inv;
    float lm = 0.f;
    for (int d = 0; d < D_; d++) lm += g_mtsum[d] * predw[l * D_ + d];
    g_logit_mt[l] = lm * inv + predb[l];
}

// ---------------- compaction -------------------------------------------------

__global__ void k_count(const int* __restrict__ ex) {
    int b = blockIdx.x * blockDim.x + threadIdx.x;
    if (b >= B_) return;
    int n = 0;
    for (int s = 0; s < S_; s++) n += (ex[b * S_ + s] != 0);
    g_nexist[b] = n;
}

__global__ void k_scan() {   // single block of 1024 threads, 4 values each
    __shared__ int sm[1024];
    int tid = threadIdx.x;
    int v[4];
    int loc = 0;
    #pragma unroll
    for (int i = 0; i < 4; i++) { v[i] = g_nexist[tid * 4 + i]; loc += v[i]; }
    sm[tid] = loc;
    __syncthreads();
    for (int off = 1; off < 1024; off <<= 1) {
        int add = (tid >= off) ? sm[tid - off] : 0;
        __syncthreads();
        sm[tid] += add;
        __syncthreads();
    }
    int run = sm[tid] - loc;   // exclusive prefix
    #pragma unroll
    for (int i = 0; i < 4; i++) { g_start[tid * 4 + i] = run; run += v[i]; }
    if (tid == 1023) g_start[B_] = run;
}

__global__ void k_rowidx(const int* __restrict__ ex) {
    int b = blockIdx.x * blockDim.x + threadIdx.x;
    if (b >= B_) return;
    int p = g_start[b];
    for (int s = 0; s < S_; s++)
        if (ex[b * S_ + s] != 0) g_rowidx[p++] = b * S_ + s;
}

// ---------------- main scores GEMM: Y[r,c] = cls[rowidx[r],:] . P[c,:] -------
// BM=128, BN=96, BK=16, 256 threads, 8x6 per thread.
// `cls` loads are scalar (no 16B alignment guarantee on harness pointers) and
// use a CLAMPED index so no out-of-range address is ever formed.
__global__ void __launch_bounds__(256) k_gemm(const float* __restrict__ cls) {
    const int total = g_start[B_];
    const int m0 = blockIdx.y * 128;
    if (m0 >= total) return;
    const int n0 = blockIdx.x * 96;
    __shared__ __align__(16) float As[16][128];
    __shared__ __align__(16) float Bs[16][96];
    __shared__ int rsrc[128];
    int tid = threadIdx.x;
    if (tid < 128) {
        int r = m0 + tid;
        rsrc[tid] = (r < total) ? g_rowidx[r] : -1;
    }
    __syncthreads();
    float acc[8][6];
    #pragma unroll
    for (int i = 0; i < 8; i++)
        #pragma unroll
        for (int j = 0; j < 6; j++) acc[i][j] = 0.f;
    int ty = tid >> 4, tx = tid & 15;
    for (int k0 = 0; k0 < D_; k0 += 16) {
        #pragma unroll
        for (int i = 0; i < 2; i++) {
            int idx = i * 256 + tid;
            int row = idx >> 2, c0 = (idx & 3) * 4;
            int src = rsrc[row];
            int srcc = (src >= 0) ? src : 0;              // clamp: always in-bounds
            const float* sp = cls + (size_t)srcc * D_ + k0 + c0;
            #pragma unroll
            for (int j = 0; j < 4; j++) {
                float v = sp[j];                          // scalar LDG.32, in-bounds
                As[c0 + j][row] = (src >= 0) ? v : 0.f;
            }
        }
        #pragma unroll
        for (int i = 0; i < 2; i++) {
            int idx = i * 256 + tid;
            if (idx < 384) {
                int row = idx >> 2, c4 = idx & 3;
                float4 v = *(const float4*)(g_P + (size_t)(n0 + row) * D_ + k0 + c4 * 4);
                Bs[c4 * 4 + 0][row] = v.x; Bs[c4 * 4 + 1][row] = v.y;
                Bs[c4 * 4 + 2][row] = v.z; Bs[c4 * 4 + 3][row] = v.w;
            }
        }
        __syncthreads();
        #pragma unroll
        for (int k = 0; k < 16; k++) {
            float a[8], bb[6];
            #pragma unroll
            for (int i = 0; i < 8; i++) a[i] = As[k][ty * 8 + i];
            #pragma unroll
            for (int j = 0; j < 6; j++) bb[j] = Bs[k][tx * 6 + j];
            #pragma unroll
            for (int i = 0; i < 8; i++)
                #pragma unroll
                for (int j = 0; j < 6; j++) acc[i][j] += a[i] * bb[j];
        }
        __syncthreads();
    }
    #pragma unroll
    for (int i = 0; i < 8; i++) {
        int r = m0 + ty * 8 + i;
        if (r < total) {
            float* yp = g_Y + (size_t)r * CP_ + n0 + tx * 6;
            #pragma unroll
            for (int j = 0; j < 6; j++) yp[j] = acc[i][j];
        }
    }
}

// ---------------- per-sample attention + reduction ---------------------------
__global__ void __launch_bounds__(128) k_attn(const float* __restrict__ cls,
                                              const int* __restrict__ ex) {
    int b = blockIdx.x;
    int tid = threadIdx.x;
    __shared__ float Ys[S_][C_];
    __shared__ float shk[H_][S_];
    __shared__ float qbs[C_];
    __shared__ int ke[S_], qm[S_];
    __shared__ int info[3];
    if (tid == 0) {
        int ne = 0, nm = 0;
        for (int s = 0; s < S_; s++) {
            if (ex[b * S_ + s] != 0) ke[ne++] = s; else qm[nm++] = s;
        }
        info[0] = ne; info[1] = nm; info[2] = g_start[b];
    }
    for (int i = tid; i < C_; i += 128) qbs[i] = g_qb[i];
    for (int i = tid; i < H_ * S_; i += 128) (&shk[0][0])[i] = 0.f;
    __syncthreads();
    int ne = info[0], nm = info[1], st = info[2];
    if (ne == 0) {   // all-missing sample: U row must be deterministic zeros
        for (int i = tid; i < UD_; i += 128) g_U[(size_t)b * UD_ + i] = 0.f;
        return;
    }
    for (int i = tid; i < ne * C_; i += 128) {
        int k = i / C_, c = i % C_;
        Ys[k][c] = g_Y[(size_t)(st + k) * CP_ + c];
    }
    __syncthreads();
    const float scale = rsqrtf((float)HD_);
    // softmax per (head, missing query); accumulate attention weights into s_hk
    for (int p = tid; p < H_ * nm; p += 128) {
        int h = p / nm, qi = p % nm;
        int c = h * S_ + qm[qi];
        float qb = qbs[c];
        float mx = -3.0e38f;
        for (int k = 0; k < ne; k++) mx = fmaxf(mx, scale * (Ys[k][c] + qb));
        float sum = 0.f;
        for (int k = 0; k < ne; k++) sum += expf(scale * (Ys[k][c] + qb) - mx);
        float inv = 1.f / sum;
        for (int k = 0; k < ne; k++) {
            float a = expf(scale * (Ys[k][c] + qb) - mx) * inv;
            atomicAdd(&shk[h][k], a);
        }
    }
    __syncthreads();
    // U[b] = [cls_sum | u_h = sum_k s_hk * cls(existing k)]
    for (int ch = 0; ch < D_ / 128; ch++) {
        int d = ch * 128 + tid;
        float cs = 0.f;
        float au[H_];
        #pragma unroll
        for (int h = 0; h < H_; h++) au[h] = 0.f;
        for (int k = 0; k < ne; k++) {
            float c = cls[((size_t)b * S_ + ke[k]) * D_ + d];   // scalar load
            cs += c;
            #pragma unroll
            for (int h = 0; h < H_; h++) au[h] += shk[h][k] * c;
        }
        size_t ub = (size_t)b * UD_;
        g_U[ub + d] = cs;
        #pragma unroll
        for (int h = 0; h < H_; h++) g_U[ub + D_ + (size_t)h * D_ + d] = au[h];
    }
}

// ---------------- final logits GEMM + epilogue --------------------------------
__global__ void k_zero(float* out) {
    int i = blockIdx.x * blockDim.x + threadIdx.x;
    if (i < B_ * L_) out[i] = 0.f;
}

#define KSPLIT 8
#define KSLICE (UD_ / KSPLIT)   // 864
// logits += U[64 rows] @ Wbig^T over a K slice (split-K with atomic add)
// Bs padded to 64 columns: thread tx reads Bs[k][tx*4 .. tx*4+3], tx up to 15
// -> column 63. (The 56-wide version read out of bounds -> illegal access.)
__global__ void __launch_bounds__(256) k_final(float* __restrict__ out) {
    int m0 = blockIdx.x * 64;
    int koff0 = blockIdx.y * KSLICE;
    __shared__ __align__(16) float As[16][64];
    __shared__ __align__(16) float Bs[16][64];
    int tid = threadIdx.x;
    int ty = tid >> 4, tx = tid & 15;
    float acc[4][4];
    #pragma unroll
    for (int i = 0; i < 4; i++)
        #pragma unroll
        for (int j = 0; j < 4; j++) acc[i][j] = 0.f;
    for (int k0 = 0; k0 < KSLICE; k0 += 16) {
        int kb = koff0 + k0;
        #pragma unroll
        for (int i = 0; i < 4; i++) {
            int id = i * 256 + tid;
            int m = id >> 4, k = id & 15;
            As[k][m] = g_U[(size_t)(m0 + m) * UD_ + kb + k];
        }
        #pragma unroll
        for (int i = 0; i < 4; i++) {
            int id = i * 256 + tid;
            int k = id >> 6, n = id & 63;
            Bs[k][n] = (n < L_) ? g_Wbig[(size_t)n * UD_ + kb + k] : 0.f;
        }
        __syncthreads();
        #pragma unroll
        for (int k = 0; k < 16; k++) {
            float4 a4 = *(const float4*)&As[k][ty * 4];
            float4 b4 = *(const float4*)&Bs[k][tx * 4];
            float a[4] = {a4.x, a4.y, a4.z, a4.w};
            float bb[4] = {b4.x, b4.y, b4.z, b4.w};
            #pragma unroll
            for (int i = 0; i < 4; i++)
                #pragma unroll
                for (int j = 0; j < 4; j++) acc[i][j] += a[i] * bb[j];
        }
        __syncthreads();
    }
    #pragma unroll
    for (int i = 0; i < 4; i++) {
        int m = m0 + ty * 4 + i;
        #pragma unroll
        for (int j = 0; j < 4; j++) {
            int n = tx * 4 + j;
            if (n < L_) atomicAdd(&out[(size_t)m * L_ + n], acc[i][j]);
        }
    }
}

__global__ void k_epi(float* __restrict__ out, const float* __restrict__ predb) {
    int b = blockIdx.x;
    int l = threadIdx.x;
    if (l >= L_) return;
    int ne = g_nexist[b];
    if (ne == 0) out[(size_t)b * L_ + l] = g_logit_mt[l];
    else out[(size_t)b * L_ + l] += (float)(S_ - ne) * g_cbias[l] + predb[l];
}

// ---------------- launch ------------------------------------------------------
extern "C" void kernel_launch(void* const* d_in, const int* in_sizes, int n_in,
                              void* d_out, int out_size) {
    // Identify inputs by unique element counts (robust to ordering), with a
    // positional fallback if anything fails to match.
    const float *cls = 0, *mt = 0, *ipw = 0, *ipb = 0, *outw = 0, *outb = 0,
                *predw = 0, *predb = 0;
    const int* ex = 0;
    for (int i = 0; i < n_in; i++) {
        switch (in_sizes[i]) {
            case B_ * S_ * D_:  cls   = (const float*)d_in[i]; break;  // 72351744
            case S_ * D_:       mt    = (const float*)d_in[i]; break;  // 17664
            case 3 * D_ * D_:   ipw   = (const float*)d_in[i]; break;  // 1769472
            case 3 * D_:        ipb   = (const float*)d_in[i]; break;  // 2304
            case D_ * D_:       outw  = (const float*)d_in[i]; break;  // 589824
            case D_:            outb  = (const float*)d_in[i]; break;  // 768
            case L_ * D_:       predw = (const float*)d_in[i]; break;  // 38400
            case L_:            predb = (const float*)d_in[i]; break;  // 50
            case B_ * S_:       ex    = (const int*)d_in[i];   break;  // 94208
        }
    }
    if (!cls || !mt || !ipw || !ipb || !outw || !outb || !predw || !predb || !ex) {
        cls   = (const float*)d_in[0];
        mt    = (const float*)d_in[1];
        ipw   = (const float*)d_in[2];
        ipb   = (const float*)d_in[3];
        outw  = (const float*)d_in[4];
        outb  = (const float*)d_in[5];
        predw = (const float*)d_in[6];
        predb = (const float*)d_in[7];
        ex    = (const int*)d_in[8];
    }
    float* out = (float*)d_out;

    // precompute folded weights
    k_qmiss<<<S_, 256>>>(mt, ipw, ipb);
    k_P<<<dim3(3, C_), 256>>>(ipw, ipb);
    k_Ppad<<<((CP_ - C_) * D_ + 255) / 256, 256>>>();
    k_wcp<<<dim3(3, L_), 256>>>(predw, outw);
    k_wbig<<<dim3(27, L_), 256>>>(predw, ipw);
    k_mtsum<<<1, D_>>>(mt);
    k_lvec<<<1, 64>>>(predw, predb, ipb, outb);

    // compaction of existing (b,s) rows
    k_count<<<B_ / 256, 256>>>(ex);
    k_scan<<<1, 1024>>>();
    k_rowidx<<<B_ / 256, 256>>>(ex);

    // main pipeline
    k_gemm<<<dim3(2, (B_ * S_) / 128), 256>>>(cls);
    k_attn<<<B_, 128>>>(cls, ex);
    k_zero<<<(B_ * L_ + 255) / 256, 256>>>(out);
    k_final<<<dim3(B_ / 64, KSPLIT), 256>>>(out);
    k_epi<<<B_, 64>>>(out, predb);
}

// round 6
// speedup vs baseline: 1.3594x; 1.3594x over previous
#include <cuda_runtime.h>
#include <math.h>
#include <stdint.h>

// Problem constants
#define B_  4096
#define S_  23
#define D_  768
#define H_  8
#define HD_ 96
#define L_  50
#define C_  184      // H_*S_ score columns
#define CP_ 192      // padded score columns
#define UD_ 6912     // 9*D_ : [cls_sum | u_0..u_7]

// ---------------- packed f32x2 FMA (Blackwell: only reachable via PTX) -------
__device__ __forceinline__ unsigned long long ffma2(unsigned long long a,
                                                    unsigned long long b,
                                                    unsigned long long c) {
    unsigned long long d;
    asm("fma.rn.f32x2 %0, %1, %2, %3;" : "=l"(d) : "l"(a), "l"(b), "l"(c));
    return d;
}
__device__ __forceinline__ float f2_lo(unsigned long long v) {
    return __uint_as_float((unsigned)(v & 0xffffffffull));
}
__device__ __forceinline__ float f2_hi(unsigned long long v) {
    return __uint_as_float((unsigned)(v >> 32));
}

// ---------------- scratch (device globals; 16B-aligned) ----------------------
__device__ __align__(16) float g_qmiss[S_ * D_];
__device__ __align__(16) float g_P[CP_ * D_];
__device__ __align__(16) float g_qb[C_];
__device__ __align__(16) float g_Wcp[L_ * D_];
__device__ __align__(16) float g_Wbig[(size_t)L_ * UD_];
__device__ __align__(16) float g_cbias[L_ + 2];
__device__ __align__(16) float g_logit_mt[L_ + 2];
__device__ __align__(16) float g_mtsum[D_];
__device__ __align__(16) int   g_nexist[B_];
__device__ __align__(16) int   g_start[B_ + 4];
__device__ __align__(16) int   g_rowidx[B_ * S_];
__device__ __align__(16) float g_Y[(size_t)B_ * S_ * CP_];
__device__ __align__(16) float g_U[(size_t)B_ * UD_];

// ---------------- precompute kernels -----------------------------------------

// qmiss[q,:] = missing_table[q,:] @ Wq^T + bq   (grid (6, S), 128 thr, 4-way ILP)
__global__ void k_qmiss(const float* __restrict__ mt, const float* __restrict__ ipw,
                        const float* __restrict__ ipb) {
    int q = blockIdx.y;
    __shared__ float row[D_];
    for (int i = threadIdx.x; i < D_; i += 128) row[i] = mt[q * D_ + i];
    __syncthreads();
    int o = blockIdx.x * 128 + threadIdx.x;
    const float* w = ipw + (size_t)o * D_;
    float a0 = 0.f, a1 = 0.f, a2 = 0.f, a3 = 0.f;
    #pragma unroll 8
    for (int d = 0; d < 192; d++) {
        a0 += row[d      ] * w[d      ];
        a1 += row[d + 192] * w[d + 192];
        a2 += row[d + 384] * w[d + 384];
        a3 += row[d + 576] * w[d + 576];
    }
    g_qmiss[q * D_ + o] = ipb[o] + ((a0 + a1) + (a2 + a3));
}

// P[c=h*S+q, d] = sum_j qmiss[q, h*96+j] * Wk[h*96+j, d];  qb[c] = qmiss_h . bk_h
__global__ void k_P(const float* __restrict__ ipw, const float* __restrict__ ipb) {
    int c = blockIdx.y;
    int h = c / S_, q = c % S_;
    __shared__ float qr[HD_];
    if (threadIdx.x < HD_) qr[threadIdx.x] = g_qmiss[q * D_ + h * HD_ + threadIdx.x];
    __syncthreads();
    int d = blockIdx.x * blockDim.x + threadIdx.x;
    const float* wk = ipw + (size_t)D_ * D_;
    float acc = 0.f;
    #pragma unroll 8
    for (int j = 0; j < HD_; j++) acc += qr[j] * wk[(size_t)(h * HD_ + j) * D_ + d];
    g_P[(size_t)c * D_ + d] = acc;
    if (blockIdx.x == 0 && threadIdx.x == 0) {
        const float* bk = ipb + D_;
        float s = 0.f;
        for (int j = 0; j < HD_; j++) s += qr[j] * bk[h * HD_ + j];
        g_qb[c] = s;
    }
}

__global__ void k_Ppad() {
    int i = blockIdx.x * blockDim.x + threadIdx.x;
    if (i < (CP_ - C_) * D_) g_P[(size_t)C_ * D_ + i] = 0.f;
}

// Wcp[l,:] = pred_w[l,:] @ out_proj_w    (grid (6, L), 128 thr, 4-way ILP)
__global__ void k_wcp(const float* __restrict__ predw, const float* __restrict__ outw) {
    int l = blockIdx.y;
    __shared__ float pr[D_];
    for (int i = threadIdx.x; i < D_; i += 128) pr[i] = predw[l * D_ + i];
    __syncthreads();
    int d = blockIdx.x * 128 + threadIdx.x;
    float a0 = 0.f, a1 = 0.f, a2 = 0.f, a3 = 0.f;
    #pragma unroll 8
    for (int m = 0; m < 192; m++) {
        a0 += pr[m      ] * outw[(size_t)(m      ) * D_ + d];
        a1 += pr[m + 192] * outw[(size_t)(m + 192) * D_ + d];
        a2 += pr[m + 384] * outw[(size_t)(m + 384) * D_ + d];
        a3 += pr[m + 576] * outw[(size_t)(m + 576) * D_ + d];
    }
    g_Wcp[l * D_ + d] = (a0 + a1) + (a2 + a3);
}

// Wbig[l, 0:768] = pred_w[l,:]/S ; Wbig[l, 768+h*768+d] = (Wcp[l,h*96:].Wv_h[:,d])/S
__global__ void k_wbig(const float* __restrict__ predw, const float* __restrict__ ipw) {
    int l = blockIdx.y;
    __shared__ float wc[D_];
    for (int i = threadIdx.x; i < D_; i += blockDim.x) wc[i] = g_Wcp[l * D_ + i];
    __syncthreads();
    int col = blockIdx.x * blockDim.x + threadIdx.x;
    const float inv = 1.f / (float)S_;
    float v;
    if (col < D_) {
        v = predw[l * D_ + col];
    } else {
        int h = (col - D_) / D_, d = (col - D_) % D_;
        const float* wv = ipw + (size_t)2 * D_ * D_;
        float acc = 0.f;
        #pragma unroll 8
        for (int j = 0; j < HD_; j++) acc += wc[h * HD_ + j] * wv[(size_t)(h * HD_ + j) * D_ + d];
        v = acc;
    }
    g_Wbig[(size_t)l * UD_ + col] = v * inv;
}

__global__ void k_mtsum(const float* __restrict__ mt) {
    int d = threadIdx.x;
    float s = 0.f;
    for (int q = 0; q < S_; q++) s += mt[q * D_ + d];
    g_mtsum[d] = s;
}

__global__ void k_lvec(const float* __restrict__ predw, const float* __restrict__ predb,
                       const float* __restrict__ ipb, const float* __restrict__ outb) {
    int l = threadIdx.x;
    if (l >= L_) return;
    const float inv = 1.f / (float)S_;
    const float* bv = ipb + 2 * D_;
    float cb = 0.f;
    for (int i = 0; i < D_; i++) cb += bv[i] * g_Wcp[l * D_ + i];
    for (int m = 0; m < D_; m++) cb += outb[m] * predw[l * D_ + m];
    g_cbias[l] = cb * inv;
    float lm = 0.f;
    for (int d = 0; d < D_; d++) lm += g_mtsum[d] * predw[l * D_ + d];
    g_logit_mt[l] = lm * inv + predb[l];
}

// ---------------- compaction --------------------------------------------------

__global__ void k_count(const int* __restrict__ ex) {
    int b = blockIdx.x * blockDim.x + threadIdx.x;
    if (b >= B_) return;
    int n = 0;
    for (int s = 0; s < S_; s++) n += (ex[b * S_ + s] != 0);
    g_nexist[b] = n;
}

__global__ void k_scan() {
    __shared__ int sm[1024];
    int tid = threadIdx.x;
    int v[4];
    int loc = 0;
    #pragma unroll
    for (int i = 0; i < 4; i++) { v[i] = g_nexist[tid * 4 + i]; loc += v[i]; }
    sm[tid] = loc;
    __syncthreads();
    for (int off = 1; off < 1024; off <<= 1) {
        int add = (tid >= off) ? sm[tid - off] : 0;
        __syncthreads();
        sm[tid] += add;
        __syncthreads();
    }
    int run = sm[tid] - loc;
    #pragma unroll
    for (int i = 0; i < 4; i++) { g_start[tid * 4 + i] = run; run += v[i]; }
    if (tid == 1023) g_start[B_] = run;
}

__global__ void k_rowidx(const int* __restrict__ ex) {
    int b = blockIdx.x * blockDim.x + threadIdx.x;
    if (b >= B_) return;
    int p = g_start[b];
    for (int s = 0; s < S_; s++)
        if (ex[b * S_ + s] != 0) g_rowidx[p++] = b * S_ + s;
}

// ---------------- main scores GEMM: Y[r,c] = cls[rowidx[r],:] . P[c,:] --------
// BM=128, BN=192 (all columns), BK=16, 256 threads, 8x12 per thread via FFMA2.
// A stored duplicated in shared (float2(a,a)) so both FFMA2 operands load as
// packed 64-bit lanes. Register-staged prefetch of the next K-tile.
__global__ void __launch_bounds__(256) k_gemm(const float* __restrict__ cls, int vec_ok) {
    const int total = g_start[B_];
    const int m0 = blockIdx.x * 128;
    if (m0 >= total) return;
    __shared__ __align__(16) float2 As2[16][128];   // 16 KB, duplicated pairs
    __shared__ __align__(16) float  Bs[16][192];    // 12 KB
    __shared__ int rsrc[128];
    int tid = threadIdx.x;
    if (tid < 128) {
        int r = m0 + tid;
        rsrc[tid] = (r < total) ? g_rowidx[r] : -1;
    }
    __syncthreads();

    int tx = tid & 15, ty = tid >> 4;   // tx: 12-col group, ty: 8-row group
    unsigned long long acc[8][6];
    #pragma unroll
    for (int i = 0; i < 8; i++)
        #pragma unroll
        for (int j = 0; j < 6; j++) acc[i][j] = 0ull;

    // prefetch registers
    float4 pa[2], pb[3];
    int arow[2];

    // A: 2048 floats / 256 thr = 8 (2 float4); B: 3072 / 256 = 12 (3 float4)
    #pragma unroll
    for (int i = 0; i < 2; i++) {
        int idx = i * 256 + tid;
        arow[i] = idx >> 2;
    }

    auto load_tile = [&](int k0) {
        #pragma unroll
        for (int i = 0; i < 2; i++) {
            int idx = i * 256 + tid;
            int row = idx >> 2, c0 = (idx & 3) * 4;
            int src = rsrc[row];
            float4 v = make_float4(0.f, 0.f, 0.f, 0.f);
            if (src >= 0) {
                const float* sp = cls + (size_t)src * D_ + k0 + c0;
                if (vec_ok) v = *(const float4*)sp;
                else { v.x = sp[0]; v.y = sp[1]; v.z = sp[2]; v.w = sp[3]; }
            }
            pa[i] = v;
        }
        #pragma unroll
        for (int i = 0; i < 3; i++) {
            int idx = i * 256 + tid;
            int n = idx >> 2, c4 = idx & 3;
            pb[i] = *(const float4*)(g_P + (size_t)n * D_ + k0 + c4 * 4);
        }
    };

    auto store_tile = [&]() {
        #pragma unroll
        for (int i = 0; i < 2; i++) {
            int idx = i * 256 + tid;
            int row = idx >> 2, c0 = (idx & 3) * 4;
            float4 v = pa[i];
            As2[c0 + 0][row] = make_float2(v.x, v.x);
            As2[c0 + 1][row] = make_float2(v.y, v.y);
            As2[c0 + 2][row] = make_float2(v.z, v.z);
            As2[c0 + 3][row] = make_float2(v.w, v.w);
        }
        #pragma unroll
        for (int i = 0; i < 3; i++) {
            int idx = i * 256 + tid;
            int n = idx >> 2, c4 = idx & 3;
            float4 v = pb[i];
            Bs[c4 * 4 + 0][n] = v.x;
            Bs[c4 * 4 + 1][n] = v.y;
            Bs[c4 * 4 + 2][n] = v.z;
            Bs[c4 * 4 + 3][n] = v.w;
        }
    };

    load_tile(0);
    for (int k0 = 0; k0 < D_; k0 += 16) {
        store_tile();
        __syncthreads();
        if (k0 + 16 < D_) load_tile(k0 + 16);   // in flight during compute
        #pragma unroll
        for (int k = 0; k < 16; k++) {
            const ulonglong2* ap = (const ulonglong2*)&As2[k][ty * 8];
            ulonglong2 A0 = ap[0], A1 = ap[1], A2 = ap[2], A3 = ap[3];
            unsigned long long a2[8] = {A0.x, A0.y, A1.x, A1.y, A2.x, A2.y, A3.x, A3.y};
            const ulonglong2* bp = (const ulonglong2*)&Bs[k][tx * 12];
            ulonglong2 B0 = bp[0], B1 = bp[1], B2 = bp[2];
            unsigned long long b2[6] = {B0.x, B0.y, B1.x, B1.y, B2.x, B2.y};
            #pragma unroll
            for (int i = 0; i < 8; i++)
                #pragma unroll
                for (int j = 0; j < 6; j++)
                    acc[i][j] = ffma2(a2[i], b2[j], acc[i][j]);
        }
        __syncthreads();
    }
    #pragma unroll
    for (int i = 0; i < 8; i++) {
        int r = m0 + ty * 8 + i;
        if (r < total) {
            unsigned long long* yp = (unsigned long long*)(g_Y + (size_t)r * CP_ + tx * 12);
            ulonglong2 s0; s0.x = acc[i][0]; s0.y = acc[i][1];
            ulonglong2 s1; s1.x = acc[i][2]; s1.y = acc[i][3];
            ulonglong2 s2; s2.x = acc[i][4]; s2.y = acc[i][5];
            ((ulonglong2*)yp)[0] = s0;
            ((ulonglong2*)yp)[1] = s1;
            ((ulonglong2*)yp)[2] = s2;
        }
    }
}

// ---------------- per-sample attention + reduction ----------------------------
__global__ void __launch_bounds__(128) k_attn(const float* __restrict__ cls,
                                              const int* __restrict__ ex) {
    int b = blockIdx.x;
    int tid = threadIdx.x;
    __shared__ float Ys[S_][C_];
    __shared__ float shk[H_][S_];
    __shared__ float qbs[C_];
    __shared__ int ke[S_], qm[S_];
    __shared__ int info[3];
    if (tid == 0) {
        int ne = 0, nm = 0;
        for (int s = 0; s < S_; s++) {
            if (ex[b * S_ + s] != 0) ke[ne++] = s; else qm[nm++] = s;
        }
        info[0] = ne; info[1] = nm; info[2] = g_start[b];
    }
    for (int i = tid; i < C_; i += 128) qbs[i] = g_qb[i];
    for (int i = tid; i < H_ * S_; i += 128) (&shk[0][0])[i] = 0.f;
    __syncthreads();
    int ne = info[0], nm = info[1], st = info[2];
    if (ne == 0) {
        for (int i = tid; i < UD_; i += 128) g_U[(size_t)b * UD_ + i] = 0.f;
        return;
    }
    for (int i = tid; i < ne * C_; i += 128) {
        int k = i / C_, c = i % C_;
        Ys[k][c] = g_Y[(size_t)(st + k) * CP_ + c];
    }
    __syncthreads();
    const float scale = rsqrtf((float)HD_);
    for (int p = tid; p < H_ * nm; p += 128) {
        int h = p / nm, qi = p % nm;
        int c = h * S_ + qm[qi];
        float qb = qbs[c];
        float mx = -3.0e38f;
        for (int k = 0; k < ne; k++) mx = fmaxf(mx, scale * (Ys[k][c] + qb));
        float sum = 0.f;
        for (int k = 0; k < ne; k++) sum += expf(scale * (Ys[k][c] + qb) - mx);
        float inv = 1.f / sum;
        for (int k = 0; k < ne; k++) {
            float a = expf(scale * (Ys[k][c] + qb) - mx) * inv;
            atomicAdd(&shk[h][k], a);
        }
    }
    __syncthreads();
    for (int ch = 0; ch < D_ / 128; ch++) {
        int d = ch * 128 + tid;
        float cs = 0.f;
        float au[H_];
        #pragma unroll
        for (int h = 0; h < H_; h++) au[h] = 0.f;
        for (int k = 0; k < ne; k++) {
            float c = cls[((size_t)b * S_ + ke[k]) * D_ + d];
            cs += c;
            #pragma unroll
            for (int h = 0; h < H_; h++) au[h] += shk[h][k] * c;
        }
        size_t ub = (size_t)b * UD_;
        g_U[ub + d] = cs;
        #pragma unroll
        for (int h = 0; h < H_; h++) g_U[ub + D_ + (size_t)h * D_ + d] = au[h];
    }
}

// ---------------- final logits GEMM + epilogue --------------------------------
__global__ void k_zero(float* out) {
    int i = blockIdx.x * blockDim.x + threadIdx.x;
    if (i < B_ * L_) out[i] = 0.f;
}

#define KSPLIT 8
#define KSLICE (UD_ / KSPLIT)   // 864
// logits += U[128 rows] @ Wbig^T over a K slice. BM=128, BN=64(pad of 50),
// 256 threads, 4x8 per thread via FFMA2, register-staged prefetch.
__global__ void __launch_bounds__(256) k_final(float* __restrict__ out) {
    int m0 = blockIdx.x * 128;
    int koff0 = blockIdx.y * KSLICE;
    __shared__ __align__(16) float2 As2[16][128];   // 16 KB duplicated
    __shared__ __align__(16) float  Bs[16][64];     // 4 KB
    int tid = threadIdx.x;
    int tx = tid & 7, ty = tid >> 3;   // tx: 8-col group, ty: 4-row group (0..31)
    unsigned long long acc[4][4];
    #pragma unroll
    for (int i = 0; i < 4; i++)
        #pragma unroll
        for (int j = 0; j < 4; j++) acc[i][j] = 0ull;

    float4 fa[2], fb;

    auto load_tile = [&](int kb) {
        #pragma unroll
        for (int i = 0; i < 2; i++) {
            int idx = i * 256 + tid;
            int row = idx >> 2, c0 = (idx & 3) * 4;
            fa[i] = *(const float4*)(g_U + (size_t)(m0 + row) * UD_ + kb + c0);
        }
        {
            int n = tid >> 2, c0 = (tid & 3) * 4;
            float4 v = make_float4(0.f, 0.f, 0.f, 0.f);
            if (n < L_) v = *(const float4*)(g_Wbig + (size_t)n * UD_ + kb + c0);
            fb = v;
        }
    };
    auto store_tile = [&]() {
        #pragma unroll
        for (int i = 0; i < 2; i++) {
            int idx = i * 256 + tid;
            int row = idx >> 2, c0 = (idx & 3) * 4;
            float4 v = fa[i];
            As2[c0 + 0][row] = make_float2(v.x, v.x);
            As2[c0 + 1][row] = make_float2(v.y, v.y);
            As2[c0 + 2][row] = make_float2(v.z, v.z);
            As2[c0 + 3][row] = make_float2(v.w, v.w);
        }
        {
            int n = tid >> 2, c0 = (tid & 3) * 4;
            float4 v = fb;
            Bs[c0 + 0][n] = v.x;
            Bs[c0 + 1][n] = v.y;
            Bs[c0 + 2][n] = v.z;
            Bs[c0 + 3][n] = v.w;
        }
    };

    load_tile(koff0);
    for (int k0 = 0; k0 < KSLICE; k0 += 16) {
        store_tile();
        __syncthreads();
        if (k0 + 16 < KSLICE) load_tile(koff0 + k0 + 16);
        #pragma unroll
        for (int k = 0; k < 16; k++) {
            const ulonglong2* ap = (const ulonglong2*)&As2[k][ty * 4];
            ulonglong2 A0 = ap[0], A1 = ap[1];
            unsigned long long a2[4] = {A0.x, A0.y, A1.x, A1.y};
            const ulonglong2* bp = (const ulonglong2*)&Bs[k][tx * 8];
            ulonglong2 B0 = bp[0], B1 = bp[1];
            unsigned long long b2[4] = {B0.x, B0.y, B1.x, B1.y};
            #pragma unroll
            for (int i = 0; i < 4; i++)
                #pragma unroll
                for (int j = 0; j < 4; j++)
                    acc[i][j] = ffma2(a2[i], b2[j], acc[i][j]);
        }
        __syncthreads();
    }
    #pragma unroll
    for (int i = 0; i < 4; i++) {
        int m = m0 + ty * 4 + i;
        #pragma unroll
        for (int j = 0; j < 4; j++) {
            int n = tx * 8 + 2 * j;
            if (n < L_)     atomicAdd(&out[(size_t)m * L_ + n],     f2_lo(acc[i][j]));
            if (n + 1 < L_) atomicAdd(&out[(size_t)m * L_ + n + 1], f2_hi(acc[i][j]));
        }
    }
}

__global__ void k_epi(float* __restrict__ out, const float* __restrict__ predb) {
    int b = blockIdx.x;
    int l = threadIdx.x;
    if (l >= L_) return;
    int ne = g_nexist[b];
    if (ne == 0) out[(size_t)b * L_ + l] = g_logit_mt[l];
    else out[(size_t)b * L_ + l] += (float)(S_ - ne) * g_cbias[l] + predb[l];
}

// ---------------- launch -------------------------------------------------------
extern "C" void kernel_launch(void* const* d_in, const int* in_sizes, int n_in,
                              void* d_out, int out_size) {
    const float *cls = 0, *mt = 0, *ipw = 0, *ipb = 0, *outw = 0, *outb = 0,
                *predw = 0, *predb = 0;
    const int* ex = 0;
    for (int i = 0; i < n_in; i++) {
        switch (in_sizes[i]) {
            case B_ * S_ * D_:  cls   = (const float*)d_in[i]; break;
            case S_ * D_:       mt    = (const float*)d_in[i]; break;
            case 3 * D_ * D_:   ipw   = (const float*)d_in[i]; break;
            case 3 * D_:        ipb   = (const float*)d_in[i]; break;
            case D_ * D_:       outw  = (const float*)d_in[i]; break;
            case D_:            outb  = (const float*)d_in[i]; break;
            case L_ * D_:       predw = (const float*)d_in[i]; break;
            case L_:            predb = (const float*)d_in[i]; break;
            case B_ * S_:       ex    = (const int*)d_in[i];   break;
        }
    }
    if (!cls || !mt || !ipw || !ipb || !outw || !outb || !predw || !predb || !ex) {
        cls   = (const float*)d_in[0];
        mt    = (const float*)d_in[1];
        ipw   = (const float*)d_in[2];
        ipb   = (const float*)d_in[3];
        outw  = (const float*)d_in[4];
        outb  = (const float*)d_in[5];
        predw = (const float*)d_in[6];
        predb = (const float*)d_in[7];
        ex    = (const int*)d_in[8];
    }
    float* out = (float*)d_out;
    int vec_ok = (((uintptr_t)cls & 15) == 0) ? 1 : 0;

    // precompute folded weights
    k_qmiss<<<dim3(6, S_), 128>>>(mt, ipw, ipb);
    k_P<<<dim3(3, C_), 256>>>(ipw, ipb);
    k_Ppad<<<((CP_ - C_) * D_ + 255) / 256, 256>>>();
    k_wcp<<<dim3(6, L_), 128>>>(predw, outw);
    k_wbig<<<dim3(27, L_), 256>>>(predw, ipw);
    k_mtsum<<<1, D_>>>(mt);
    k_lvec<<<1, 64>>>(predw, predb, ipb, outb);

    // compaction of existing (b,s) rows
    k_count<<<B_ / 256, 256>>>(ex);
    k_scan<<<1, 1024>>>();
    k_rowidx<<<B_ / 256, 256>>>(ex);

    // main pipeline
    k_gemm<<<(B_ * S_) / 128, 256>>>(cls, vec_ok);
    k_attn<<<B_, 128>>>(cls, ex);
    k_zero<<<(B_ * L_ + 255) / 256, 256>>>(out);
    k_final<<<dim3(B_ / 128, KSPLIT), 256>>>(out);
    k_epi<<<B_, 64>>>(out, predb);
}

// round 7
// speedup vs baseline: 1.4434x; 1.0618x over previous
#include <cuda_runtime.h>
#include <math.h>
#include <stdint.h>

// Problem constants
#define B_  4096
#define S_  23
#define D_  768
#define H_  8
#define HD_ 96
#define L_  50
#define C_  184      // H_*S_ score columns
#define CP_ 192      // padded score columns
#define UD_ 6912     // 9*D_ : [cls_sum | u_0..u_7]

// ---------------- packed f32x2 FMA (Blackwell: only reachable via PTX) -------
__device__ __forceinline__ unsigned long long ffma2(unsigned long long a,
                                                    unsigned long long b,
                                                    unsigned long long c) {
    unsigned long long d;
    asm("fma.rn.f32x2 %0, %1, %2, %3;" : "=l"(d) : "l"(a), "l"(b), "l"(c));
    return d;
}
__device__ __forceinline__ float f2_lo(unsigned long long v) {
    return __uint_as_float((unsigned)(v & 0xffffffffull));
}
__device__ __forceinline__ float f2_hi(unsigned long long v) {
    return __uint_as_float((unsigned)(v >> 32));
}

// ---------------- scratch (device globals; 16B-aligned) ----------------------
__device__ __align__(16) float g_qmiss[S_ * D_];
__device__ __align__(16) float g_P[CP_ * D_];
__device__ __align__(16) float g_qb[C_];
__device__ __align__(16) float g_Wcp[L_ * D_];
__device__ __align__(16) float g_Wbig[(size_t)L_ * UD_];
__device__ __align__(16) float g_cbias[L_ + 2];
__device__ __align__(16) float g_logit_mt[L_ + 2];
__device__ __align__(16) float g_mtsum[D_];
__device__ __align__(16) int   g_nexist[B_];
__device__ __align__(16) int   g_start[B_ + 4];
__device__ __align__(16) int   g_rowidx[B_ * S_];
__device__ __align__(16) float g_Y[(size_t)B_ * S_ * CP_];
__device__ __align__(16) float g_U[(size_t)B_ * UD_];

// ---------------- precompute kernels -----------------------------------------

// qmiss[q,:] = missing_table[q,:] @ Wq^T + bq.  grid (6, S), 128 thr.
// 4 independent float4 chains -> 4 LDG.128 in flight per iter.
__global__ void __launch_bounds__(128) k_qmiss(const float* __restrict__ mt,
                                               const float* __restrict__ ipw,
                                               const float* __restrict__ ipb,
                                               int vec_ok) {
    int q = blockIdx.y;
    __shared__ __align__(16) float row[D_];
    for (int i = threadIdx.x; i < D_; i += 128) row[i] = mt[q * D_ + i];
    __syncthreads();
    int o = blockIdx.x * 128 + threadIdx.x;
    const float* w = ipw + (size_t)o * D_;
    float acc;
    if (vec_ok) {
        const float4* w4 = (const float4*)w;
        const float4* r4 = (const float4*)row;
        float a0 = 0.f, a1 = 0.f, a2 = 0.f, a3 = 0.f;
        #pragma unroll 4
        for (int i = 0; i < 48; i++) {
            float4 w0 = w4[i], w1 = w4[48 + i], w2 = w4[96 + i], w3 = w4[144 + i];
            float4 r0 = r4[i], r1 = r4[48 + i], r2 = r4[96 + i], r3 = r4[144 + i];
            a0 += w0.x * r0.x + w0.y * r0.y + w0.z * r0.z + w0.w * r0.w;
            a1 += w1.x * r1.x + w1.y * r1.y + w1.z * r1.z + w1.w * r1.w;
            a2 += w2.x * r2.x + w2.y * r2.y + w2.z * r2.z + w2.w * r2.w;
            a3 += w3.x * r3.x + w3.y * r3.y + w3.z * r3.z + w3.w * r3.w;
        }
        acc = (a0 + a1) + (a2 + a3);
    } else {
        float a0 = 0.f, a1 = 0.f, a2 = 0.f, a3 = 0.f;
        #pragma unroll 8
        for (int d = 0; d < 192; d++) {
            a0 += row[d      ] * w[d      ];
            a1 += row[d + 192] * w[d + 192];
            a2 += row[d + 384] * w[d + 384];
            a3 += row[d + 576] * w[d + 576];
        }
        acc = (a0 + a1) + (a2 + a3);
    }
    g_qmiss[q * D_ + o] = ipb[o] + acc;
}

// P[c=h*S+q, d] = sum_j qmiss[q, h*96+j] * Wk[h*96+j, d];  qb[c] = qmiss_h . bk_h
// grid (3, CP_): rows c >= C_ are zero padding (written here, no extra kernel).
__global__ void k_P(const float* __restrict__ ipw, const float* __restrict__ ipb) {
    int c = blockIdx.y;
    int d = blockIdx.x * blockDim.x + threadIdx.x;
    if (c >= C_) { g_P[(size_t)c * D_ + d] = 0.f; return; }   // uniform per block
    int h = c / S_, q = c % S_;
    __shared__ float qr[HD_];
    if (threadIdx.x < HD_) qr[threadIdx.x] = g_qmiss[q * D_ + h * HD_ + threadIdx.x];
    __syncthreads();
    const float* wk = ipw + (size_t)D_ * D_;
    float acc = 0.f;
    #pragma unroll 8
    for (int j = 0; j < HD_; j++) acc += qr[j] * wk[(size_t)(h * HD_ + j) * D_ + d];
    g_P[(size_t)c * D_ + d] = acc;
    if (blockIdx.x == 0 && threadIdx.x == 0) {
        const float* bk = ipb + D_;
        float s = 0.f;
        for (int j = 0; j < HD_; j++) s += qr[j] * bk[h * HD_ + j];
        g_qb[c] = s;
    }
}

__global__ void k_wcpzero() {
    int i = blockIdx.x * blockDim.x + threadIdx.x;
    if (i < L_ * D_) g_Wcp[i] = 0.f;
}

// Wcp = pred_w @ out_proj_w as tiled GEMM with k-split atomics.
// grid (6 dslice, 8 kslice), 256 thr; each block does two 48-m subtiles.
__global__ void __launch_bounds__(256) k_wcp(const float* __restrict__ predw,
                                             const float* __restrict__ outw) {
    __shared__ float ps[48][65];    // ps[m][l], l padded to 64
    __shared__ float os[48][132];   // os[m][d]
    int tid = threadIdx.x;
    int d0 = blockIdx.x * 128;
    int dg = tid & 15, lg = tid >> 4;    // d = d0 + dg*8 + j ; l = lg*4 + i
    float acc[4][8];
    #pragma unroll
    for (int i = 0; i < 4; i++)
        #pragma unroll
        for (int j = 0; j < 8; j++) acc[i][j] = 0.f;
    for (int t = 0; t < 2; t++) {
        int m0 = blockIdx.y * 96 + t * 48;
        __syncthreads();
        // ps: 64 l x 48 m = 3072 / 256 = 12 per thread, coalesced over m
        #pragma unroll
        for (int i = 0; i < 12; i++) {
            int idx = i * 256 + tid;
            int l = idx / 48, m = idx % 48;
            ps[m][l] = (l < L_) ? predw[(size_t)l * D_ + m0 + m] : 0.f;
        }
        // os: 48 m x 128 d = 6144 / 256 = 24 per thread, coalesced over d
        #pragma unroll
        for (int i = 0; i < 24; i++) {
            int idx = i * 256 + tid;
            int m = idx / 128, d = idx % 128;
            os[m][d] = outw[(size_t)(m0 + m) * D_ + d0 + d];
        }
        __syncthreads();
        #pragma unroll 4
        for (int m = 0; m < 48; m++) {
            float b[8];
            float4 b0 = *(const float4*)&os[m][dg * 8];
            float4 b1 = *(const float4*)&os[m][dg * 8 + 4];
            b[0]=b0.x; b[1]=b0.y; b[2]=b0.z; b[3]=b0.w;
            b[4]=b1.x; b[5]=b1.y; b[6]=b1.z; b[7]=b1.w;
            float a[4];
            #pragma unroll
            for (int i = 0; i < 4; i++) a[i] = ps[m][lg * 4 + i];
            #pragma unroll
            for (int i = 0; i < 4; i++)
                #pragma unroll
                for (int j = 0; j < 8; j++) acc[i][j] += a[i] * b[j];
        }
    }
    #pragma unroll
    for (int i = 0; i < 4; i++) {
        int l = lg * 4 + i;
        if (l < L_)
            #pragma unroll
            for (int j = 0; j < 8; j++)
                atomicAdd(&g_Wcp[(size_t)l * D_ + d0 + dg * 8 + j], acc[i][j]);
    }
}

// Wbig: by==0 -> copy pred_w/S into cols [0,768); by=1..8 -> head GEMM
// Wbig[l, 768+h*768+d] = (sum_j Wcp[l,h*96+j] * Wv[h*96+j, d]) / S
__global__ void __launch_bounds__(256) k_wbig(const float* __restrict__ predw,
                                              const float* __restrict__ ipw) {
    const float inv = 1.f / (float)S_;
    int tid = threadIdx.x;
    int d0 = blockIdx.x * 128;
    if (blockIdx.y == 0) {
        // copy predw/S : 50 x 128 elements
        for (int i = 0; i < 25; i++) {
            int idx = i * 256 + tid;
            int l = idx / 128, d = idx % 128;
            g_Wbig[(size_t)l * UD_ + d0 + d] = predw[(size_t)l * D_ + d0 + d] * inv;
        }
        return;
    }
    int h = blockIdx.y - 1;
    const float* wv = ipw + (size_t)2 * D_ * D_;
    __shared__ float ws[48][65];    // ws[j][l]
    __shared__ float vs[48][132];   // vs[j][d]
    int dg = tid & 15, lg = tid >> 4;
    float acc[4][8];
    #pragma unroll
    for (int i = 0; i < 4; i++)
        #pragma unroll
        for (int j = 0; j < 8; j++) acc[i][j] = 0.f;
    for (int t = 0; t < 2; t++) {
        int j0 = t * 48;
        __syncthreads();
        #pragma unroll
        for (int i = 0; i < 12; i++) {
            int idx = i * 256 + tid;
            int l = idx / 48, j = idx % 48;
            ws[j][l] = (l < L_) ? g_Wcp[(size_t)l * D_ + h * HD_ + j0 + j] : 0.f;
        }
        #pragma unroll
        for (int i = 0; i < 24; i++) {
            int idx = i * 256 + tid;
            int j = idx / 128, d = idx % 128;
            vs[j][d] = wv[(size_t)(h * HD_ + j0 + j) * D_ + d0 + d];
        }
        __syncthreads();
        #pragma unroll 4
        for (int j = 0; j < 48; j++) {
            float b[8];
            float4 b0 = *(const float4*)&vs[j][dg * 8];
            float4 b1 = *(const float4*)&vs[j][dg * 8 + 4];
            b[0]=b0.x; b[1]=b0.y; b[2]=b0.z; b[3]=b0.w;
            b[4]=b1.x; b[5]=b1.y; b[6]=b1.z; b[7]=b1.w;
            float a[4];
            #pragma unroll
            for (int i = 0; i < 4; i++) a[i] = ws[j][lg * 4 + i];
            #pragma unroll
            for (int i = 0; i < 4; i++)
                #pragma unroll
                for (int jj = 0; jj < 8; jj++) acc[i][jj] += a[i] * b[jj];
        }
    }
    #pragma unroll
    for (int i = 0; i < 4; i++) {
        int l = lg * 4 + i;
        if (l < L_)
            #pragma unroll
            for (int j = 0; j < 8; j++)
                g_Wbig[(size_t)l * UD_ + D_ + h * D_ + d0 + dg * 8 + j] = acc[i][j] * inv;
    }
}

__global__ void k_mtsum(const float* __restrict__ mt) {
    int d = threadIdx.x;
    float s = 0.f;
    for (int q = 0; q < S_; q++) s += mt[q * D_ + d];
    g_mtsum[d] = s;
}

__global__ void k_lvec(const float* __restrict__ predw, const float* __restrict__ predb,
                       const float* __restrict__ ipb, const float* __restrict__ outb) {
    int l = threadIdx.x;
    if (l >= L_) return;
    const float inv = 1.f / (float)S_;
    const float* bv = ipb + 2 * D_;
    float cb = 0.f;
    for (int i = 0; i < D_; i++) cb += bv[i] * g_Wcp[l * D_ + i];
    for (int m = 0; m < D_; m++) cb += outb[m] * predw[l * D_ + m];
    g_cbias[l] = cb * inv;
    float lm = 0.f;
    for (int d = 0; d < D_; d++) lm += g_mtsum[d] * predw[l * D_ + d];
    g_logit_mt[l] = lm * inv + predb[l];
}

// ---------------- compaction: count + prefix scan in one kernel --------------
__global__ void k_scan(const int* __restrict__ ex) {
    __shared__ int sm[1024];
    int tid = threadIdx.x;
    int v[4];
    int loc = 0;
    #pragma unroll
    for (int i = 0; i < 4; i++) {
        int b = tid * 4 + i;
        int n = 0;
        for (int s = 0; s < S_; s++) n += (ex[b * S_ + s] != 0);
        g_nexist[b] = n;
        v[i] = n; loc += n;
    }
    sm[tid] = loc;
    __syncthreads();
    for (int off = 1; off < 1024; off <<= 1) {
        int add = (tid >= off) ? sm[tid - off] : 0;
        __syncthreads();
        sm[tid] += add;
        __syncthreads();
    }
    int run = sm[tid] - loc;
    #pragma unroll
    for (int i = 0; i < 4; i++) { g_start[tid * 4 + i] = run; run += v[i]; }
    if (tid == 1023) g_start[B_] = run;
}

__global__ void k_rowidx(const int* __restrict__ ex) {
    int b = blockIdx.x * blockDim.x + threadIdx.x;
    if (b >= B_) return;
    int p = g_start[b];
    for (int s = 0; s < S_; s++)
        if (ex[b * S_ + s] != 0) g_rowidx[p++] = b * S_ + s;
}

// ---------------- main scores GEMM: Y[r,c] = cls[rowidx[r],:] . P[c,:] --------
// BM=128, BN=192, BK=16, 256 threads, 8x12 per thread via FFMA2.
__global__ void __launch_bounds__(256) k_gemm(const float* __restrict__ cls, int vec_ok) {
    const int total = g_start[B_];
    const int m0 = blockIdx.x * 128;
    if (m0 >= total) return;
    __shared__ __align__(16) float2 As2[16][128];
    __shared__ __align__(16) float  Bs[16][192];
    __shared__ int rsrc[128];
    int tid = threadIdx.x;
    if (tid < 128) {
        int r = m0 + tid;
        rsrc[tid] = (r < total) ? g_rowidx[r] : -1;
    }
    __syncthreads();

    int tx = tid & 15, ty = tid >> 4;
    unsigned long long acc[8][6];
    #pragma unroll
    for (int i = 0; i < 8; i++)
        #pragma unroll
        for (int j = 0; j < 6; j++) acc[i][j] = 0ull;

    float4 pa[2], pb[3];

    auto load_tile = [&](int k0) {
        #pragma unroll
        for (int i = 0; i < 2; i++) {
            int idx = i * 256 + tid;
            int row = idx >> 2, c0 = (idx & 3) * 4;
            int src = rsrc[row];
            float4 v = make_float4(0.f, 0.f, 0.f, 0.f);
            if (src >= 0) {
                const float* sp = cls + (size_t)src * D_ + k0 + c0;
                if (vec_ok) v = *(const float4*)sp;
                else { v.x = sp[0]; v.y = sp[1]; v.z = sp[2]; v.w = sp[3]; }
            }
            pa[i] = v;
        }
        #pragma unroll
        for (int i = 0; i < 3; i++) {
            int idx = i * 256 + tid;
            int n = idx >> 2, c4 = idx & 3;
            pb[i] = *(const float4*)(g_P + (size_t)n * D_ + k0 + c4 * 4);
        }
    };
    auto store_tile = [&]() {
        #pragma unroll
        for (int i = 0; i < 2; i++) {
            int idx = i * 256 + tid;
            int row = idx >> 2, c0 = (idx & 3) * 4;
            float4 v = pa[i];
            As2[c0 + 0][row] = make_float2(v.x, v.x);
            As2[c0 + 1][row] = make_float2(v.y, v.y);
            As2[c0 + 2][row] = make_float2(v.z, v.z);
            As2[c0 + 3][row] = make_float2(v.w, v.w);
        }
        #pragma unroll
        for (int i = 0; i < 3; i++) {
            int idx = i * 256 + tid;
            int n = idx >> 2, c4 = idx & 3;
            float4 v = pb[i];
            Bs[c4 * 4 + 0][n] = v.x;
            Bs[c4 * 4 + 1][n] = v.y;
            Bs[c4 * 4 + 2][n] = v.z;
            Bs[c4 * 4 + 3][n] = v.w;
        }
    };

    load_tile(0);
    for (int k0 = 0; k0 < D_; k0 += 16) {
        store_tile();
        __syncthreads();
        if (k0 + 16 < D_) load_tile(k0 + 16);
        #pragma unroll
        for (int k = 0; k < 16; k++) {
            const ulonglong2* ap = (const ulonglong2*)&As2[k][ty * 8];
            ulonglong2 A0 = ap[0], A1 = ap[1], A2 = ap[2], A3 = ap[3];
            unsigned long long a2[8] = {A0.x, A0.y, A1.x, A1.y, A2.x, A2.y, A3.x, A3.y};
            const ulonglong2* bp = (const ulonglong2*)&Bs[k][tx * 12];
            ulonglong2 B0 = bp[0], B1 = bp[1], B2 = bp[2];
            unsigned long long b2[6] = {B0.x, B0.y, B1.x, B1.y, B2.x, B2.y};
            #pragma unroll
            for (int i = 0; i < 8; i++)
                #pragma unroll
                for (int j = 0; j < 6; j++)
                    acc[i][j] = ffma2(a2[i], b2[j], acc[i][j]);
        }
        __syncthreads();
    }
    #pragma unroll
    for (int i = 0; i < 8; i++) {
        int r = m0 + ty * 8 + i;
        if (r < total) {
            unsigned long long* yp = (unsigned long long*)(g_Y + (size_t)r * CP_ + tx * 12);
            ulonglong2 s0; s0.x = acc[i][0]; s0.y = acc[i][1];
            ulonglong2 s1; s1.x = acc[i][2]; s1.y = acc[i][3];
            ulonglong2 s2; s2.x = acc[i][4]; s2.y = acc[i][5];
            ((ulonglong2*)yp)[0] = s0;
            ((ulonglong2*)yp)[1] = s1;
            ((ulonglong2*)yp)[2] = s2;
        }
    }
}

// ---------------- per-sample attention + reduction ----------------------------
__global__ void __launch_bounds__(128) k_attn(const float* __restrict__ cls,
                                              const int* __restrict__ ex) {
    int b = blockIdx.x;
    int tid = threadIdx.x;
    __shared__ float Ys[S_][C_];
    __shared__ float shk[H_][S_];
    __shared__ float qbs[C_];
    __shared__ int ke[S_], qm[S_];
    __shared__ int info[3];
    if (tid == 0) {
        int ne = 0, nm = 0;
        for (int s = 0; s < S_; s++) {
            if (ex[b * S_ + s] != 0) ke[ne++] = s; else qm[nm++] = s;
        }
        info[0] = ne; info[1] = nm; info[2] = g_start[b];
    }
    for (int i = tid; i < C_; i += 128) qbs[i] = g_qb[i];
    for (int i = tid; i < H_ * S_; i += 128) (&shk[0][0])[i] = 0.f;
    __syncthreads();
    int ne = info[0], nm = info[1], st = info[2];
    if (ne == 0) {
        for (int i = tid; i < UD_; i += 128) g_U[(size_t)b * UD_ + i] = 0.f;
        return;
    }
    for (int i = tid; i < ne * C_; i += 128) {
        int k = i / C_, c = i % C_;
        Ys[k][c] = g_Y[(size_t)(st + k) * CP_ + c];
    }
    __syncthreads();
    const float scale = rsqrtf((float)HD_);
    // softmax per (head, missing query); each c owned by exactly one thread,
    // so Ys[:,c] is reused as scratch across the three passes.
    for (int p = tid; p < H_ * nm; p += 128) {
        int h = p / nm, qi = p % nm;
        int c = h * S_ + qm[qi];
        float qb = qbs[c];
        float mx = -3.0e38f;
        for (int k = 0; k < ne; k++) {
            float t = scale * (Ys[k][c] + qb);
            Ys[k][c] = t;
            mx = fmaxf(mx, t);
        }
        float sum = 0.f;
        for (int k = 0; k < ne; k++) {
            float e = expf(Ys[k][c] - mx);
            Ys[k][c] = e;
            sum += e;
        }
        float inv = 1.f / sum;
        for (int k = 0; k < ne; k++)
            atomicAdd(&shk[h][k], Ys[k][c] * inv);
    }
    __syncthreads();
    for (int ch = 0; ch < D_ / 128; ch++) {
        int d = ch * 128 + tid;
        float cs = 0.f;
        float au[H_];
        #pragma unroll
        for (int h = 0; h < H_; h++) au[h] = 0.f;
        for (int k = 0; k < ne; k++) {
            float c = cls[((size_t)b * S_ + ke[k]) * D_ + d];
            cs += c;
            #pragma unroll
            for (int h = 0; h < H_; h++) au[h] += shk[h][k] * c;
        }
        size_t ub = (size_t)b * UD_;
        g_U[ub + d] = cs;
        #pragma unroll
        for (int h = 0; h < H_; h++) g_U[ub + D_ + (size_t)h * D_ + d] = au[h];
    }
}

// ---------------- final logits GEMM + epilogue --------------------------------
__global__ void k_zero(float* out) {
    int i = blockIdx.x * blockDim.x + threadIdx.x;
    if (i < B_ * L_) out[i] = 0.f;
}

#define KSPLIT 8
#define KSLICE (UD_ / KSPLIT)   // 864
__global__ void __launch_bounds__(256) k_final(float* __restrict__ out) {
    int m0 = blockIdx.x * 128;
    int koff0 = blockIdx.y * KSLICE;
    __shared__ __align__(16) float2 As2[16][128];
    __shared__ __align__(16) float  Bs[16][64];
    int tid = threadIdx.x;
    int tx = tid & 7, ty = tid >> 3;
    unsigned long long acc[4][4];
    #pragma unroll
    for (int i = 0; i < 4; i++)
        #pragma unroll
        for (int j = 0; j < 4; j++) acc[i][j] = 0ull;

    float4 fa[2], fb;

    auto load_tile = [&](int kb) {
        #pragma unroll
        for (int i = 0; i < 2; i++) {
            int idx = i * 256 + tid;
            int row = idx >> 2, c0 = (idx & 3) * 4;
            fa[i] = *(const float4*)(g_U + (size_t)(m0 + row) * UD_ + kb + c0);
        }
        {
            int n = tid >> 2, c0 = (tid & 3) * 4;
            float4 v = make_float4(0.f, 0.f, 0.f, 0.f);
            if (n < L_) v = *(const float4*)(g_Wbig + (size_t)n * UD_ + kb + c0);
            fb = v;
        }
    };
    auto store_tile = [&]() {
        #pragma unroll
        for (int i = 0; i < 2; i++) {
            int idx = i * 256 + tid;
            int row = idx >> 2, c0 = (idx & 3) * 4;
            float4 v = fa[i];
            As2[c0 + 0][row] = make_float2(v.x, v.x);
            As2[c0 + 1][row] = make_float2(v.y, v.y);
            As2[c0 + 2][row] = make_float2(v.z, v.z);
            As2[c0 + 3][row] = make_float2(v.w, v.w);
        }
        {
            int n = tid >> 2, c0 = (tid & 3) * 4;
            float4 v = fb;
            Bs[c0 + 0][n] = v.x;
            Bs[c0 + 1][n] = v.y;
            Bs[c0 + 2][n] = v.z;
            Bs[c0 + 3][n] = v.w;
        }
    };

    load_tile(koff0);
    for (int k0 = 0; k0 < KSLICE; k0 += 16) {
        store_tile();
        __syncthreads();
        if (k0 + 16 < KSLICE) load_tile(koff0 + k0 + 16);
        #pragma unroll
        for (int k = 0; k < 16; k++) {
            const ulonglong2* ap = (const ulonglong2*)&As2[k][ty * 4];
            ulonglong2 A0 = ap[0], A1 = ap[1];
            unsigned long long a2[4] = {A0.x, A0.y, A1.x, A1.y};
            const ulonglong2* bp = (const ulonglong2*)&Bs[k][tx * 8];
            ulonglong2 B0 = bp[0], B1 = bp[1];
            unsigned long long b2[4] = {B0.x, B0.y, B1.x, B1.y};
            #pragma unroll
            for (int i = 0; i < 4; i++)
                #pragma unroll
                for (int j = 0; j < 4; j++)
                    acc[i][j] = ffma2(a2[i], b2[j], acc[i][j]);
        }
        __syncthreads();
    }
    #pragma unroll
    for (int i = 0; i < 4; i++) {
        int m = m0 + ty * 4 + i;
        #pragma unroll
        for (int j = 0; j < 4; j++) {
            int n = tx * 8 + 2 * j;
            if (n < L_)     atomicAdd(&out[(size_t)m * L_ + n],     f2_lo(acc[i][j]));
            if (n + 1 < L_) atomicAdd(&out[(size_t)m * L_ + n + 1], f2_hi(acc[i][j]));
        }
    }
}

__global__ void k_epi(float* __restrict__ out, const float* __restrict__ predb) {
    int b = blockIdx.x;
    int l = threadIdx.x;
    if (l >= L_) return;
    int ne = g_nexist[b];
    if (ne == 0) out[(size_t)b * L_ + l] = g_logit_mt[l];
    else out[(size_t)b * L_ + l] += (float)(S_ - ne) * g_cbias[l] + predb[l];
}

// ---------------- launch -------------------------------------------------------
extern "C" void kernel_launch(void* const* d_in, const int* in_sizes, int n_in,
                              void* d_out, int out_size) {
    const float *cls = 0, *mt = 0, *ipw = 0, *ipb = 0, *outw = 0, *outb = 0,
                *predw = 0, *predb = 0;
    const int* ex = 0;
    for (int i = 0; i < n_in; i++) {
        switch (in_sizes[i]) {
            case B_ * S_ * D_:  cls   = (const float*)d_in[i]; break;
            case S_ * D_:       mt    = (const float*)d_in[i]; break;
            case 3 * D_ * D_:   ipw   = (const float*)d_in[i]; break;
            case 3 * D_:        ipb   = (const float*)d_in[i]; break;
            case D_ * D_:       outw  = (const float*)d_in[i]; break;
            case D_:            outb  = (const float*)d_in[i]; break;
            case L_ * D_:       predw = (const float*)d_in[i]; break;
            case L_:            predb = (const float*)d_in[i]; break;
            case B_ * S_:       ex    = (const int*)d_in[i];   break;
        }
    }
    if (!cls || !mt || !ipw || !ipb || !outw || !outb || !predw || !predb || !ex) {
        cls   = (const float*)d_in[0];
        mt    = (const float*)d_in[1];
        ipw   = (const float*)d_in[2];
        ipb   = (const float*)d_in[3];
        outw  = (const float*)d_in[4];
        outb  = (const float*)d_in[5];
        predw = (const float*)d_in[6];
        predb = (const float*)d_in[7];
        ex    = (const int*)d_in[8];
    }
    float* out = (float*)d_out;
    int vec_cls = (((uintptr_t)cls & 15) == 0) ? 1 : 0;
    int vec_ipw = (((uintptr_t)ipw & 15) == 0) ? 1 : 0;

    // Launch order matters: ncu profiles launch #6 (-s 5 -c 1) -> k_gemm.
    k_qmiss<<<dim3(6, S_), 128>>>(mt, ipw, ipb, vec_ipw);        // 1
    k_P<<<dim3(3, CP_), 256>>>(ipw, ipb);                        // 2 (incl. pad)
    k_scan<<<1, 1024>>>(ex);                                     // 3 (count+scan)
    k_rowidx<<<B_ / 256, 256>>>(ex);                             // 4
    k_wcpzero<<<150, 256>>>();                                   // 5
    k_gemm<<<(B_ * S_) / 128, 256>>>(cls, vec_cls);              // 6  <- profiled
    k_wcp<<<dim3(6, 8), 256>>>(predw, outw);                     // 7
    k_wbig<<<dim3(6, 9), 256>>>(predw, ipw);                     // 8
    k_mtsum<<<1, D_>>>(mt);                                      // 9
    k_lvec<<<1, 64>>>(predw, predb, ipb, outb);                  // 10
    k_attn<<<B_, 128>>>(cls, ex);                                // 11
    k_zero<<<(B_ * L_ + 255) / 256, 256>>>(out);                 // 12
    k_final<<<dim3(B_ / 128, KSPLIT), 256>>>(out);               // 13
    k_epi<<<B_, 64>>>(out, predb);                               // 14
}

// round 8
// speedup vs baseline: 1.4437x; 1.0002x over previous
#include <cuda_runtime.h>
#include <math.h>
#include <stdint.h>

// Problem constants
#define B_  4096
#define S_  23
#define D_  768
#define H_  8
#define HD_ 96
#define L_  50
#define C_  184      // H_*S_ score columns
#define CP_ 192      // padded score columns
#define UD_ 6912     // 9*D_ : [cls_sum | u_0..u_7]

// ---------------- packed f32x2 FMA (Blackwell: only reachable via PTX) -------
__device__ __forceinline__ unsigned long long ffma2(unsigned long long a,
                                                    unsigned long long b,
                                                    unsigned long long c) {
    unsigned long long d;
    asm("fma.rn.f32x2 %0, %1, %2, %3;" : "=l"(d) : "l"(a), "l"(b), "l"(c));
    return d;
}
__device__ __forceinline__ float f2_lo(unsigned long long v) {
    return __uint_as_float((unsigned)(v & 0xffffffffull));
}
__device__ __forceinline__ float f2_hi(unsigned long long v) {
    return __uint_as_float((unsigned)(v >> 32));
}

// ---------------- scratch (device globals; 16B-aligned) ----------------------
__device__ __align__(16) float g_qmiss[S_ * D_];
__device__ __align__(16) float g_P[CP_ * D_];
__device__ __align__(16) float g_qb[C_];
__device__ __align__(16) float g_Wcp[L_ * D_];
__device__ __align__(16) float g_Wbig[(size_t)L_ * UD_];
__device__ __align__(16) float g_cbias[L_ + 2];
__device__ __align__(16) float g_logit_mt[L_ + 2];
__device__ __align__(16) float g_mtsum[D_];
__device__ __align__(16) int   g_nexist[B_];
__device__ __align__(16) int   g_start[B_ + 4];
__device__ __align__(16) int   g_rowidx[B_ * S_];
__device__ __align__(16) float g_Y[(size_t)B_ * S_ * CP_];
__device__ __align__(16) float g_U[(size_t)B_ * UD_];

// ---------------- precompute kernels -----------------------------------------

// qmiss[q,:] = missing_table[q,:] @ Wq^T + bq.  grid (6, S), 128 thr.
// 4 independent float4 chains -> 4 LDG.128 in flight per iter.
__global__ void __launch_bounds__(128) k_qmiss(const float* __restrict__ mt,
                                               const float* __restrict__ ipw,
                                               const float* __restrict__ ipb,
                                               int vec_ok) {
    int q = blockIdx.y;
    __shared__ __align__(16) float row[D_];
    for (int i = threadIdx.x; i < D_; i += 128) row[i] = mt[q * D_ + i];
    __syncthreads();
    int o = blockIdx.x * 128 + threadIdx.x;
    const float* w = ipw + (size_t)o * D_;
    float acc;
    if (vec_ok) {
        const float4* w4 = (const float4*)w;
        const float4* r4 = (const float4*)row;
        float a0 = 0.f, a1 = 0.f, a2 = 0.f, a3 = 0.f;
        #pragma unroll 4
        for (int i = 0; i < 48; i++) {
            float4 w0 = w4[i], w1 = w4[48 + i], w2 = w4[96 + i], w3 = w4[144 + i];
            float4 r0 = r4[i], r1 = r4[48 + i], r2 = r4[96 + i], r3 = r4[144 + i];
            a0 += w0.x * r0.x + w0.y * r0.y + w0.z * r0.z + w0.w * r0.w;
            a1 += w1.x * r1.x + w1.y * r1.y + w1.z * r1.z + w1.w * r1.w;
            a2 += w2.x * r2.x + w2.y * r2.y + w2.z * r2.z + w2.w * r2.w;
            a3 += w3.x * r3.x + w3.y * r3.y + w3.z * r3.z + w3.w * r3.w;
        }
        acc = (a0 + a1) + (a2 + a3);
    } else {
        float a0 = 0.f, a1 = 0.f, a2 = 0.f, a3 = 0.f;
        #pragma unroll 8
        for (int d = 0; d < 192; d++) {
            a0 += row[d      ] * w[d      ];
            a1 += row[d + 192] * w[d + 192];
            a2 += row[d + 384] * w[d + 384];
            a3 += row[d + 576] * w[d + 576];
        }
        acc = (a0 + a1) + (a2 + a3);
    }
    g_qmiss[q * D_ + o] = ipb[o] + acc;
}

// P[c=h*S+q, d] = sum_j qmiss[q, h*96+j] * Wk[h*96+j, d];  qb[c] = qmiss_h . bk_h
// grid (3, CP_): rows c >= C_ are zero padding (written here, no extra kernel).
__global__ void k_P(const float* __restrict__ ipw, const float* __restrict__ ipb) {
    int c = blockIdx.y;
    int d = blockIdx.x * blockDim.x + threadIdx.x;
    if (c >= C_) { g_P[(size_t)c * D_ + d] = 0.f; return; }   // uniform per block
    int h = c / S_, q = c % S_;
    __shared__ float qr[HD_];
    if (threadIdx.x < HD_) qr[threadIdx.x] = g_qmiss[q * D_ + h * HD_ + threadIdx.x];
    __syncthreads();
    const float* wk = ipw + (size_t)D_ * D_;
    float acc = 0.f;
    #pragma unroll 8
    for (int j = 0; j < HD_; j++) acc += qr[j] * wk[(size_t)(h * HD_ + j) * D_ + d];
    g_P[(size_t)c * D_ + d] = acc;
    if (blockIdx.x == 0 && threadIdx.x == 0) {
        const float* bk = ipb + D_;
        float s = 0.f;
        for (int j = 0; j < HD_; j++) s += qr[j] * bk[h * HD_ + j];
        g_qb[c] = s;
    }
}

__global__ void k_wcpzero() {
    int i = blockIdx.x * blockDim.x + threadIdx.x;
    if (i < L_ * D_) g_Wcp[i] = 0.f;
}

// Wcp = pred_w @ out_proj_w as tiled GEMM with k-split atomics.
// grid (6 dslice, 8 kslice), 256 thr; each block does two 48-m subtiles.
__global__ void __launch_bounds__(256) k_wcp(const float* __restrict__ predw,
                                             const float* __restrict__ outw) {
    __shared__ float ps[48][65];    // ps[m][l], l padded to 64
    __shared__ float os[48][132];   // os[m][d]
    int tid = threadIdx.x;
    int d0 = blockIdx.x * 128;
    int dg = tid & 15, lg = tid >> 4;    // d = d0 + dg*8 + j ; l = lg*4 + i
    float acc[4][8];
    #pragma unroll
    for (int i = 0; i < 4; i++)
        #pragma unroll
        for (int j = 0; j < 8; j++) acc[i][j] = 0.f;
    for (int t = 0; t < 2; t++) {
        int m0 = blockIdx.y * 96 + t * 48;
        __syncthreads();
        // ps: 64 l x 48 m = 3072 / 256 = 12 per thread, coalesced over m
        #pragma unroll
        for (int i = 0; i < 12; i++) {
            int idx = i * 256 + tid;
            int l = idx / 48, m = idx % 48;
            ps[m][l] = (l < L_) ? predw[(size_t)l * D_ + m0 + m] : 0.f;
        }
        // os: 48 m x 128 d = 6144 / 256 = 24 per thread, coalesced over d
        #pragma unroll
        for (int i = 0; i < 24; i++) {
            int idx = i * 256 + tid;
            int m = idx / 128, d = idx % 128;
            os[m][d] = outw[(size_t)(m0 + m) * D_ + d0 + d];
        }
        __syncthreads();
        #pragma unroll 4
        for (int m = 0; m < 48; m++) {
            float b[8];
            float4 b0 = *(const float4*)&os[m][dg * 8];
            float4 b1 = *(const float4*)&os[m][dg * 8 + 4];
            b[0]=b0.x; b[1]=b0.y; b[2]=b0.z; b[3]=b0.w;
            b[4]=b1.x; b[5]=b1.y; b[6]=b1.z; b[7]=b1.w;
            float a[4];
            #pragma unroll
            for (int i = 0; i < 4; i++) a[i] = ps[m][lg * 4 + i];
            #pragma unroll
            for (int i = 0; i < 4; i++)
                #pragma unroll
                for (int j = 0; j < 8; j++) acc[i][j] += a[i] * b[j];
        }
    }
    #pragma unroll
    for (int i = 0; i < 4; i++) {
        int l = lg * 4 + i;
        if (l < L_)
            #pragma unroll
            for (int j = 0; j < 8; j++)
                atomicAdd(&g_Wcp[(size_t)l * D_ + d0 + dg * 8 + j], acc[i][j]);
    }
}

// Wbig: by==0 -> copy pred_w/S into cols [0,768); by=1..8 -> head GEMM
// Wbig[l, 768+h*768+d] = (sum_j Wcp[l,h*96+j] * Wv[h*96+j, d]) / S
__global__ void __launch_bounds__(256) k_wbig(const float* __restrict__ predw,
                                              const float* __restrict__ ipw) {
    const float inv = 1.f / (float)S_;
    int tid = threadIdx.x;
    int d0 = blockIdx.x * 128;
    if (blockIdx.y == 0) {
        // copy predw/S : 50 x 128 elements
        for (int i = 0; i < 25; i++) {
            int idx = i * 256 + tid;
            int l = idx / 128, d = idx % 128;
            g_Wbig[(size_t)l * UD_ + d0 + d] = predw[(size_t)l * D_ + d0 + d] * inv;
        }
        return;
    }
    int h = blockIdx.y - 1;
    const float* wv = ipw + (size_t)2 * D_ * D_;
    __shared__ float ws[48][65];    // ws[j][l]
    __shared__ float vs[48][132];   // vs[j][d]
    int dg = tid & 15, lg = tid >> 4;
    float acc[4][8];
    #pragma unroll
    for (int i = 0; i < 4; i++)
        #pragma unroll
        for (int j = 0; j < 8; j++) acc[i][j] = 0.f;
    for (int t = 0; t < 2; t++) {
        int j0 = t * 48;
        __syncthreads();
        #pragma unroll
        for (int i = 0; i < 12; i++) {
            int idx = i * 256 + tid;
            int l = idx / 48, j = idx % 48;
            ws[j][l] = (l < L_) ? g_Wcp[(size_t)l * D_ + h * HD_ + j0 + j] : 0.f;
        }
        #pragma unroll
        for (int i = 0; i < 24; i++) {
            int idx = i * 256 + tid;
            int j = idx / 128, d = idx % 128;
            vs[j][d] = wv[(size_t)(h * HD_ + j0 + j) * D_ + d0 + d];
        }
        __syncthreads();
        #pragma unroll 4
        for (int j = 0; j < 48; j++) {
            float b[8];
            float4 b0 = *(const float4*)&vs[j][dg * 8];
            float4 b1 = *(const float4*)&vs[j][dg * 8 + 4];
            b[0]=b0.x; b[1]=b0.y; b[2]=b0.z; b[3]=b0.w;
            b[4]=b1.x; b[5]=b1.y; b[6]=b1.z; b[7]=b1.w;
            float a[4];
            #pragma unroll
            for (int i = 0; i < 4; i++) a[i] = ws[j][lg * 4 + i];
            #pragma unroll
            for (int i = 0; i < 4; i++)
                #pragma unroll
                for (int jj = 0; jj < 8; jj++) acc[i][jj] += a[i] * b[jj];
        }
    }
    #pragma unroll
    for (int i = 0; i < 4; i++) {
        int l = lg * 4 + i;
        if (l < L_)
            #pragma unroll
            for (int j = 0; j < 8; j++)
                g_Wbig[(size_t)l * UD_ + D_ + h * D_ + d0 + dg * 8 + j] = acc[i][j] * inv;
    }
}

__global__ void k_mtsum(const float* __restrict__ mt) {
    int d = threadIdx.x;
    float s = 0.f;
    for (int q = 0; q < S_; q++) s += mt[q * D_ + d];
    g_mtsum[d] = s;
}

__global__ void k_lvec(const float* __restrict__ predw, const float* __restrict__ predb,
                       const float* __restrict__ ipb, const float* __restrict__ outb) {
    int l = threadIdx.x;
    if (l >= L_) return;
    const float inv = 1.f / (float)S_;
    const float* bv = ipb + 2 * D_;
    float cb = 0.f;
    for (int i = 0; i < D_; i++) cb += bv[i] * g_Wcp[l * D_ + i];
    for (int m = 0; m < D_; m++) cb += outb[m] * predw[l * D_ + m];
    g_cbias[l] = cb * inv;
    float lm = 0.f;
    for (int d = 0; d < D_; d++) lm += g_mtsum[d] * predw[l * D_ + d];
    g_logit_mt[l] = lm * inv + predb[l];
}

// ---------------- compaction: count + prefix scan in one kernel --------------
__global__ void k_scan(const int* __restrict__ ex) {
    __shared__ int sm[1024];
    int tid = threadIdx.x;
    int v[4];
    int loc = 0;
    #pragma unroll
    for (int i = 0; i < 4; i++) {
        int b = tid * 4 + i;
        int n = 0;
        for (int s = 0; s < S_; s++) n += (ex[b * S_ + s] != 0);
        g_nexist[b] = n;
        v[i] = n; loc += n;
    }
    sm[tid] = loc;
    __syncthreads();
    for (int off = 1; off < 1024; off <<= 1) {
        int add = (tid >= off) ? sm[tid - off] : 0;
        __syncthreads();
        sm[tid] += add;
        __syncthreads();
    }
    int run = sm[tid] - loc;
    #pragma unroll
    for (int i = 0; i < 4; i++) { g_start[tid * 4 + i] = run; run += v[i]; }
    if (tid == 1023) g_start[B_] = run;
}

__global__ void k_rowidx(const int* __restrict__ ex) {
    int b = blockIdx.x * blockDim.x + threadIdx.x;
    if (b >= B_) return;
    int p = g_start[b];
    for (int s = 0; s < S_; s++)
        if (ex[b * S_ + s] != 0) g_rowidx[p++] = b * S_ + s;
}

// ---------------- main scores GEMM: Y[r,c] = cls[rowidx[r],:] . P[c,:] --------
// BM=128, BN=192, BK=16, 256 threads, 8x12 per thread via FFMA2.
__global__ void __launch_bounds__(256) k_gemm(const float* __restrict__ cls, int vec_ok) {
    const int total = g_start[B_];
    const int m0 = blockIdx.x * 128;
    if (m0 >= total) return;
    __shared__ __align__(16) float2 As2[16][128];
    __shared__ __align__(16) float  Bs[16][192];
    __shared__ int rsrc[128];
    int tid = threadIdx.x;
    if (tid < 128) {
        int r = m0 + tid;
        rsrc[tid] = (r < total) ? g_rowidx[r] : -1;
    }
    __syncthreads();

    int tx = tid & 15, ty = tid >> 4;
    unsigned long long acc[8][6];
    #pragma unroll
    for (int i = 0; i < 8; i++)
        #pragma unroll
        for (int j = 0; j < 6; j++) acc[i][j] = 0ull;

    float4 pa[2], pb[3];

    auto load_tile = [&](int k0) {
        #pragma unroll
        for (int i = 0; i < 2; i++) {
            int idx = i * 256 + tid;
            int row = idx >> 2, c0 = (idx & 3) * 4;
            int src = rsrc[row];
            float4 v = make_float4(0.f, 0.f, 0.f, 0.f);
            if (src >= 0) {
                const float* sp = cls + (size_t)src * D_ + k0 + c0;
                if (vec_ok) v = *(const float4*)sp;
                else { v.x = sp[0]; v.y = sp[1]; v.z = sp[2]; v.w = sp[3]; }
            }
            pa[i] = v;
        }
        #pragma unroll
        for (int i = 0; i < 3; i++) {
            int idx = i * 256 + tid;
            int n = idx >> 2, c4 = idx & 3;
            pb[i] = *(const float4*)(g_P + (size_t)n * D_ + k0 + c4 * 4);
        }
    };
    auto store_tile = [&]() {
        #pragma unroll
        for (int i = 0; i < 2; i++) {
            int idx = i * 256 + tid;
            int row = idx >> 2, c0 = (idx & 3) * 4;
            float4 v = pa[i];
            As2[c0 + 0][row] = make_float2(v.x, v.x);
            As2[c0 + 1][row] = make_float2(v.y, v.y);
            As2[c0 + 2][row] = make_float2(v.z, v.z);
            As2[c0 + 3][row] = make_float2(v.w, v.w);
        }
        #pragma unroll
        for (int i = 0; i < 3; i++) {
            int idx = i * 256 + tid;
            int n = idx >> 2, c4 = idx & 3;
            float4 v = pb[i];
            Bs[c4 * 4 + 0][n] = v.x;
            Bs[c4 * 4 + 1][n] = v.y;
            Bs[c4 * 4 + 2][n] = v.z;
            Bs[c4 * 4 + 3][n] = v.w;
        }
    };

    load_tile(0);
    for (int k0 = 0; k0 < D_; k0 += 16) {
        store_tile();
        __syncthreads();
        if (k0 + 16 < D_) load_tile(k0 + 16);
        #pragma unroll
        for (int k = 0; k < 16; k++) {
            const ulonglong2* ap = (const ulonglong2*)&As2[k][ty * 8];
            ulonglong2 A0 = ap[0], A1 = ap[1], A2 = ap[2], A3 = ap[3];
            unsigned long long a2[8] = {A0.x, A0.y, A1.x, A1.y, A2.x, A2.y, A3.x, A3.y};
            const ulonglong2* bp = (const ulonglong2*)&Bs[k][tx * 12];
            ulonglong2 B0 = bp[0], B1 = bp[1], B2 = bp[2];
            unsigned long long b2[6] = {B0.x, B0.y, B1.x, B1.y, B2.x, B2.y};
            #pragma unroll
            for (int i = 0; i < 8; i++)
                #pragma unroll
                for (int j = 0; j < 6; j++)
                    acc[i][j] = ffma2(a2[i], b2[j], acc[i][j]);
        }
        __syncthreads();
    }
    #pragma unroll
    for (int i = 0; i < 8; i++) {
        int r = m0 + ty * 8 + i;
        if (r < total) {
            unsigned long long* yp = (unsigned long long*)(g_Y + (size_t)r * CP_ + tx * 12);
            ulonglong2 s0; s0.x = acc[i][0]; s0.y = acc[i][1];
            ulonglong2 s1; s1.x = acc[i][2]; s1.y = acc[i][3];
            ulonglong2 s2; s2.x = acc[i][4]; s2.y = acc[i][5];
            ((ulonglong2*)yp)[0] = s0;
            ((ulonglong2*)yp)[1] = s1;
            ((ulonglong2*)yp)[2] = s2;
        }
    }
}

// ---------------- per-sample attention + reduction ----------------------------
__global__ void __launch_bounds__(128) k_attn(const float* __restrict__ cls,
                                              const int* __restrict__ ex) {
    int b = blockIdx.x;
    int tid = threadIdx.x;
    __shared__ float Ys[S_][C_];
    __shared__ float shk[H_][S_];
    __shared__ float qbs[C_];
    __shared__ int ke[S_], qm[S_];
    __shared__ int info[3];
    if (tid == 0) {
        int ne = 0, nm = 0;
        for (int s = 0; s < S_; s++) {
            if (ex[b * S_ + s] != 0) ke[ne++] = s; else qm[nm++] = s;
        }
        info[0] = ne; info[1] = nm; info[2] = g_start[b];
    }
    for (int i = tid; i < C_; i += 128) qbs[i] = g_qb[i];
    for (int i = tid; i < H_ * S_; i += 128) (&shk[0][0])[i] = 0.f;
    __syncthreads();
    int ne = info[0], nm = info[1], st = info[2];
    if (ne == 0) {
        for (int i = tid; i < UD_; i += 128) g_U[(size_t)b * UD_ + i] = 0.f;
        return;
    }
    for (int i = tid; i < ne * C_; i += 128) {
        int k = i / C_, c = i % C_;
        Ys[k][c] = g_Y[(size_t)(st + k) * CP_ + c];
    }
    __syncthreads();
    const float scale = rsqrtf((float)HD_);
    // softmax per (head, missing query); each c owned by exactly one thread,
    // so Ys[:,c] is reused as scratch across the three passes.
    for (int p = tid; p < H_ * nm; p += 128) {
        int h = p / nm, qi = p % nm;
        int c = h * S_ + qm[qi];
        float qb = qbs[c];
        float mx = -3.0e38f;
        for (int k = 0; k < ne; k++) {
            float t = scale * (Ys[k][c] + qb);
            Ys[k][c] = t;
            mx = fmaxf(mx, t);
        }
        float sum = 0.f;
        for (int k = 0; k < ne; k++) {
            float e = expf(Ys[k][c] - mx);
            Ys[k][c] = e;
            sum += e;
        }
        float inv = 1.f / sum;
        for (int k = 0; k < ne; k++)
            atomicAdd(&shk[h][k], Ys[k][c] * inv);
    }
    __syncthreads();
    for (int ch = 0; ch < D_ / 128; ch++) {
        int d = ch * 128 + tid;
        float cs = 0.f;
        float au[H_];
        #pragma unroll
        for (int h = 0; h < H_; h++) au[h] = 0.f;
        for (int k = 0; k < ne; k++) {
            float c = cls[((size_t)b * S_ + ke[k]) * D_ + d];
            cs += c;
            #pragma unroll
            for (int h = 0; h < H_; h++) au[h] += shk[h][k] * c;
        }
        size_t ub = (size_t)b * UD_;
        g_U[ub + d] = cs;
        #pragma unroll
        for (int h = 0; h < H_; h++) g_U[ub + D_ + (size_t)h * D_ + d] = au[h];
    }
}

// ---------------- final logits GEMM + epilogue --------------------------------
__global__ void k_zero(float* out) {
    int i = blockIdx.x * blockDim.x + threadIdx.x;
    if (i < B_ * L_) out[i] = 0.f;
}

#define KSPLIT 8
#define KSLICE (UD_ / KSPLIT)   // 864
__global__ void __launch_bounds__(256) k_final(float* __restrict__ out) {
    int m0 = blockIdx.x * 128;
    int koff0 = blockIdx.y * KSLICE;
    __shared__ __align__(16) float2 As2[16][128];
    __shared__ __align__(16) float  Bs[16][64];
    int tid = threadIdx.x;
    int tx = tid & 7, ty = tid >> 3;
    unsigned long long acc[4][4];
    #pragma unroll
    for (int i = 0; i < 4; i++)
        #pragma unroll
        for (int j = 0; j < 4; j++) acc[i][j] = 0ull;

    float4 fa[2], fb;

    auto load_tile = [&](int kb) {
        #pragma unroll
        for (int i = 0; i < 2; i++) {
            int idx = i * 256 + tid;
            int row = idx >> 2, c0 = (idx & 3) * 4;
            fa[i] = *(const float4*)(g_U + (size_t)(m0 + row) * UD_ + kb + c0);
        }
        {
            int n = tid >> 2, c0 = (tid & 3) * 4;
            float4 v = make_float4(0.f, 0.f, 0.f, 0.f);
            if (n < L_) v = *(const float4*)(g_Wbig + (size_t)n * UD_ + kb + c0);
            fb = v;
        }
    };
    auto store_tile = [&]() {
        #pragma unroll
        for (int i = 0; i < 2; i++) {
            int idx = i * 256 + tid;
            int row = idx >> 2, c0 = (idx & 3) * 4;
            float4 v = fa[i];
            As2[c0 + 0][row] = make_float2(v.x, v.x);
            As2[c0 + 1][row] = make_float2(v.y, v.y);
            As2[c0 + 2][row] = make_float2(v.z, v.z);
            As2[c0 + 3][row] = make_float2(v.w, v.w);
        }
        {
            int n = tid >> 2, c0 = (tid & 3) * 4;
            float4 v = fb;
            Bs[c0 + 0][n] = v.x;
            Bs[c0 + 1][n] = v.y;
            Bs[c0 + 2][n] = v.z;
            Bs[c0 + 3][n] = v.w;
        }
    };

    load_tile(koff0);
    for (int k0 = 0; k0 < KSLICE; k0 += 16) {
        store_tile();
        __syncthreads();
        if (k0 + 16 < KSLICE) load_tile(koff0 + k0 + 16);
        #pragma unroll
        for (int k = 0; k < 16; k++) {
            const ulonglong2* ap = (const ulonglong2*)&As2[k][ty * 4];
            ulonglong2 A0 = ap[0], A1 = ap[1];
            unsigned long long a2[4] = {A0.x, A0.y, A1.x, A1.y};
            const ulonglong2* bp = (const ulonglong2*)&Bs[k][tx * 8];
            ulonglong2 B0 = bp[0], B1 = bp[1];
            unsigned long long b2[4] = {B0.x, B0.y, B1.x, B1.y};
            #pragma unroll
            for (int i = 0; i < 4; i++)
                #pragma unroll
                for (int j = 0; j < 4; j++)
                    acc[i][j] = ffma2(a2[i], b2[j], acc[i][j]);
        }
        __syncthreads();
    }
    #pragma unroll
    for (int i = 0; i < 4; i++) {
        int m = m0 + ty * 4 + i;
        #pragma unroll
        for (int j = 0; j < 4; j++) {
            int n = tx * 8 + 2 * j;
            if (n < L_)     atomicAdd(&out[(size_t)m * L_ + n],     f2_lo(acc[i][j]));
            if (n + 1 < L_) atomicAdd(&out[(size_t)m * L_ + n + 1], f2_hi(acc[i][j]));
        }
    }
}

__global__ void k_epi(float* __restrict__ out, const float* __restrict__ predb) {
    int b = blockIdx.x;
    int l = threadIdx.x;
    if (l >= L_) return;
    int ne = g_nexist[b];
    if (ne == 0) out[(size_t)b * L_ + l] = g_logit_mt[l];
    else out[(size_t)b * L_ + l] += (float)(S_ - ne) * g_cbias[l] + predb[l];
}

// ---------------- launch -------------------------------------------------------
extern "C" void kernel_launch(void* const* d_in, const int* in_sizes, int n_in,
                              void* d_out, int out_size) {
    const float *cls = 0, *mt = 0, *ipw = 0, *ipb = 0, *outw = 0, *outb = 0,
                *predw = 0, *predb = 0;
    const int* ex = 0;
    for (int i = 0; i < n_in; i++) {
        switch (in_sizes[i]) {
            case B_ * S_ * D_:  cls   = (const float*)d_in[i]; break;
            case S_ * D_:       mt    = (const float*)d_in[i]; break;
            case 3 * D_ * D_:   ipw   = (const float*)d_in[i]; break;
            case 3 * D_:        ipb   = (const float*)d_in[i]; break;
            case D_ * D_:       outw  = (const float*)d_in[i]; break;
            case D_:            outb  = (const float*)d_in[i]; break;
            case L_ * D_:       predw = (const float*)d_in[i]; break;
            case L_:            predb = (const float*)d_in[i]; break;
            case B_ * S_:       ex    = (const int*)d_in[i];   break;
        }
    }
    if (!cls || !mt || !ipw || !ipb || !outw || !outb || !predw || !predb || !ex) {
        cls   = (const float*)d_in[0];
        mt    = (const float*)d_in[1];
        ipw   = (const float*)d_in[2];
        ipb   = (const float*)d_in[3];
        outw  = (const float*)d_in[4];
        outb  = (const float*)d_in[5];
        predw = (const float*)d_in[6];
        predb = (const float*)d_in[7];
        ex    = (const int*)d_in[8];
    }
    float* out = (float*)d_out;
    int vec_cls = (((uintptr_t)cls & 15) == 0) ? 1 : 0;
    int vec_ipw = (((uintptr_t)ipw & 15) == 0) ? 1 : 0;

    // Launch order matters: ncu profiles launch #6 (-s 5 -c 1) -> k_gemm.
    k_qmiss<<<dim3(6, S_), 128>>>(mt, ipw, ipb, vec_ipw);        // 1
    k_P<<<dim3(3, CP_), 256>>>(ipw, ipb);                        // 2 (incl. pad)
    k_scan<<<1, 1024>>>(ex);                                     // 3 (count+scan)
    k_rowidx<<<B_ / 256, 256>>>(ex);                             // 4
    k_wcpzero<<<150, 256>>>();                                   // 5
    k_gemm<<<(B_ * S_) / 128, 256>>>(cls, vec_cls);              // 6  <- profiled
    k_wcp<<<dim3(6, 8), 256>>>(predw, outw);                     // 7
    k_wbig<<<dim3(6, 9), 256>>>(predw, ipw);                     // 8
    k_mtsum<<<1, D_>>>(mt);                                      // 9
    k_lvec<<<1, 64>>>(predw, predb, ipb, outb);                  // 10
    k_attn<<<B_, 128>>>(cls, ex);                                // 11
    k_zero<<<(B_ * L_ + 255) / 256, 256>>>(out);                 // 12
    k_final<<<dim3(B_ / 128, KSPLIT), 256>>>(out);               // 13
    k_epi<<<B_, 64>>>(out, predb);                               // 14
}

// round 9
// speedup vs baseline: 1.4502x; 1.0045x over previous
#include <cuda_runtime.h>
#include <math.h>
#include <stdint.h>

// Problem constants
#define B_  4096
#define S_  23
#define D_  768
#define H_  8
#define HD_ 96
#define L_  50
#define C_  184      // H_*S_ score columns
#define CP_ 192      // padded score columns
#define UD_ 6912     // 9*D_ : [cls_sum | u_0..u_7]

// ---------------- packed f32x2 FMA (Blackwell: only reachable via PTX) -------
__device__ __forceinline__ unsigned long long ffma2(unsigned long long a,
                                                    unsigned long long b,
                                                    unsigned long long c) {
    unsigned long long d;
    asm("fma.rn.f32x2 %0, %1, %2, %3;" : "=l"(d) : "l"(a), "l"(b), "l"(c));
    return d;
}
__device__ __forceinline__ float f2_lo(unsigned long long v) {
    return __uint_as_float((unsigned)(v & 0xffffffffull));
}
__device__ __forceinline__ float f2_hi(unsigned long long v) {
    return __uint_as_float((unsigned)(v >> 32));
}

// ---------------- scratch (device globals; 16B-aligned) ----------------------
__device__ __align__(16) float g_qmiss[S_ * D_];
__device__ __align__(16) float g_P[CP_ * D_];
__device__ __align__(16) float g_qb[C_];
__device__ __align__(16) float g_Wcp[L_ * D_];
__device__ __align__(16) float g_Wbig[(size_t)L_ * UD_];
__device__ __align__(16) float g_cbias[L_ + 2];
__device__ __align__(16) float g_logit_mt[L_ + 2];
__device__ __align__(16) float g_mtsum[D_];
__device__ __align__(16) int   g_nexist[B_];
__device__ __align__(16) int   g_start[B_ + 4];
__device__ __align__(16) int   g_rowidx[B_ * S_];
__device__ __align__(16) float g_Y[(size_t)B_ * S_ * CP_];
__device__ __align__(16) float g_U[(size_t)B_ * UD_];

// ---------------- precompute kernels -----------------------------------------

// qmiss[q,:] = missing_table[q,:] @ Wq^T + bq.  grid (6, S), 128 thr.
// 4 independent float4 chains -> 4 LDG.128 in flight per iter.
__global__ void __launch_bounds__(128) k_qmiss(const float* __restrict__ mt,
                                               const float* __restrict__ ipw,
                                               const float* __restrict__ ipb,
                                               int vec_ok) {
    int q = blockIdx.y;
    __shared__ __align__(16) float row[D_];
    for (int i = threadIdx.x; i < D_; i += 128) row[i] = mt[q * D_ + i];
    __syncthreads();
    int o = blockIdx.x * 128 + threadIdx.x;
    const float* w = ipw + (size_t)o * D_;
    float acc;
    if (vec_ok) {
        const float4* w4 = (const float4*)w;
        const float4* r4 = (const float4*)row;
        float a0 = 0.f, a1 = 0.f, a2 = 0.f, a3 = 0.f;
        #pragma unroll 4
        for (int i = 0; i < 48; i++) {
            float4 w0 = w4[i], w1 = w4[48 + i], w2 = w4[96 + i], w3 = w4[144 + i];
            float4 r0 = r4[i], r1 = r4[48 + i], r2 = r4[96 + i], r3 = r4[144 + i];
            a0 += w0.x * r0.x + w0.y * r0.y + w0.z * r0.z + w0.w * r0.w;
            a1 += w1.x * r1.x + w1.y * r1.y + w1.z * r1.z + w1.w * r1.w;
            a2 += w2.x * r2.x + w2.y * r2.y + w2.z * r2.z + w2.w * r2.w;
            a3 += w3.x * r3.x + w3.y * r3.y + w3.z * r3.z + w3.w * r3.w;
        }
        acc = (a0 + a1) + (a2 + a3);
    } else {
        float a0 = 0.f, a1 = 0.f, a2 = 0.f, a3 = 0.f;
        #pragma unroll 8
        for (int d = 0; d < 192; d++) {
            a0 += row[d      ] * w[d      ];
            a1 += row[d + 192] * w[d + 192];
            a2 += row[d + 384] * w[d + 384];
            a3 += row[d + 576] * w[d + 576];
        }
        acc = (a0 + a1) + (a2 + a3);
    }
    g_qmiss[q * D_ + o] = ipb[o] + acc;
}

// P[c=h*S+q, d] = sum_j qmiss[q, h*96+j] * Wk[h*96+j, d];  qb[c] = qmiss_h . bk_h
// grid (3, CP_): rows c >= C_ are zero padding (written here, no extra kernel).
__global__ void k_P(const float* __restrict__ ipw, const float* __restrict__ ipb) {
    int c = blockIdx.y;
    int d = blockIdx.x * blockDim.x + threadIdx.x;
    if (c >= C_) { g_P[(size_t)c * D_ + d] = 0.f; return; }   // uniform per block
    int h = c / S_, q = c % S_;
    __shared__ float qr[HD_];
    if (threadIdx.x < HD_) qr[threadIdx.x] = g_qmiss[q * D_ + h * HD_ + threadIdx.x];
    __syncthreads();
    const float* wk = ipw + (size_t)D_ * D_;
    float acc = 0.f;
    #pragma unroll 8
    for (int j = 0; j < HD_; j++) acc += qr[j] * wk[(size_t)(h * HD_ + j) * D_ + d];
    g_P[(size_t)c * D_ + d] = acc;
    if (blockIdx.x == 0 && threadIdx.x == 0) {
        const float* bk = ipb + D_;
        float s = 0.f;
        for (int j = 0; j < HD_; j++) s += qr[j] * bk[h * HD_ + j];
        g_qb[c] = s;
    }
}

__global__ void k_wcpzero() {
    int i = blockIdx.x * blockDim.x + threadIdx.x;
    if (i < L_ * D_) g_Wcp[i] = 0.f;
}

// Wcp = pred_w @ out_proj_w as tiled GEMM with k-split atomics.
// grid (6 dslice, 8 kslice), 256 thr; each block does two 48-m subtiles.
__global__ void __launch_bounds__(256) k_wcp(const float* __restrict__ predw,
                                             const float* __restrict__ outw) {
    __shared__ float ps[48][65];    // ps[m][l], l padded to 64
    __shared__ float os[48][132];   // os[m][d]
    int tid = threadIdx.x;
    int d0 = blockIdx.x * 128;
    int dg = tid & 15, lg = tid >> 4;    // d = d0 + dg*8 + j ; l = lg*4 + i
    float acc[4][8];
    #pragma unroll
    for (int i = 0; i < 4; i++)
        #pragma unroll
        for (int j = 0; j < 8; j++) acc[i][j] = 0.f;
    for (int t = 0; t < 2; t++) {
        int m0 = blockIdx.y * 96 + t * 48;
        __syncthreads();
        // ps: 64 l x 48 m = 3072 / 256 = 12 per thread, coalesced over m
        #pragma unroll
        for (int i = 0; i < 12; i++) {
            int idx = i * 256 + tid;
            int l = idx / 48, m = idx % 48;
            ps[m][l] = (l < L_) ? predw[(size_t)l * D_ + m0 + m] : 0.f;
        }
        // os: 48 m x 128 d = 6144 / 256 = 24 per thread, coalesced over d
        #pragma unroll
        for (int i = 0; i < 24; i++) {
            int idx = i * 256 + tid;
            int m = idx / 128, d = idx % 128;
            os[m][d] = outw[(size_t)(m0 + m) * D_ + d0 + d];
        }
        __syncthreads();
        #pragma unroll 4
        for (int m = 0; m < 48; m++) {
            float b[8];
            float4 b0 = *(const float4*)&os[m][dg * 8];
            float4 b1 = *(const float4*)&os[m][dg * 8 + 4];
            b[0]=b0.x; b[1]=b0.y; b[2]=b0.z; b[3]=b0.w;
            b[4]=b1.x; b[5]=b1.y; b[6]=b1.z; b[7]=b1.w;
            float a[4];
            #pragma unroll
            for (int i = 0; i < 4; i++) a[i] = ps[m][lg * 4 + i];
            #pragma unroll
            for (int i = 0; i < 4; i++)
                #pragma unroll
                for (int j = 0; j < 8; j++) acc[i][j] += a[i] * b[j];
        }
    }
    #pragma unroll
    for (int i = 0; i < 4; i++) {
        int l = lg * 4 + i;
        if (l < L_)
            #pragma unroll
            for (int j = 0; j < 8; j++)
                atomicAdd(&g_Wcp[(size_t)l * D_ + d0 + dg * 8 + j], acc[i][j]);
    }
}

// Wbig: by==0 -> copy pred_w/S into cols [0,768); by=1..8 -> head GEMM
// Wbig[l, 768+h*768+d] = (sum_j Wcp[l,h*96+j] * Wv[h*96+j, d]) / S
__global__ void __launch_bounds__(256) k_wbig(const float* __restrict__ predw,
                                              const float* __restrict__ ipw) {
    const float inv = 1.f / (float)S_;
    int tid = threadIdx.x;
    int d0 = blockIdx.x * 128;
    if (blockIdx.y == 0) {
        // copy predw/S : 50 x 128 elements
        for (int i = 0; i < 25; i++) {
            int idx = i * 256 + tid;
            int l = idx / 128, d = idx % 128;
            g_Wbig[(size_t)l * UD_ + d0 + d] = predw[(size_t)l * D_ + d0 + d] * inv;
        }
        return;
    }
    int h = blockIdx.y - 1;
    const float* wv = ipw + (size_t)2 * D_ * D_;
    __shared__ float ws[48][65];    // ws[j][l]
    __shared__ float vs[48][132];   // vs[j][d]
    int dg = tid & 15, lg = tid >> 4;
    float acc[4][8];
    #pragma unroll
    for (int i = 0; i < 4; i++)
        #pragma unroll
        for (int j = 0; j < 8; j++) acc[i][j] = 0.f;
    for (int t = 0; t < 2; t++) {
        int j0 = t * 48;
        __syncthreads();
        #pragma unroll
        for (int i = 0; i < 12; i++) {
            int idx = i * 256 + tid;
            int l = idx / 48, j = idx % 48;
            ws[j][l] = (l < L_) ? g_Wcp[(size_t)l * D_ + h * HD_ + j0 + j] : 0.f;
        }
        #pragma unroll
        for (int i = 0; i < 24; i++) {
            int idx = i * 256 + tid;
            int j = idx / 128, d = idx % 128;
            vs[j][d] = wv[(size_t)(h * HD_ + j0 + j) * D_ + d0 + d];
        }
        __syncthreads();
        #pragma unroll 4
        for (int j = 0; j < 48; j++) {
            float b[8];
            float4 b0 = *(const float4*)&vs[j][dg * 8];
            float4 b1 = *(const float4*)&vs[j][dg * 8 + 4];
            b[0]=b0.x; b[1]=b0.y; b[2]=b0.z; b[3]=b0.w;
            b[4]=b1.x; b[5]=b1.y; b[6]=b1.z; b[7]=b1.w;
            float a[4];
            #pragma unroll
            for (int i = 0; i < 4; i++) a[i] = ws[j][lg * 4 + i];
            #pragma unroll
            for (int i = 0; i < 4; i++)
                #pragma unroll
                for (int jj = 0; jj < 8; jj++) acc[i][jj] += a[i] * b[jj];
        }
    }
    #pragma unroll
    for (int i = 0; i < 4; i++) {
        int l = lg * 4 + i;
        if (l < L_)
            #pragma unroll
            for (int j = 0; j < 8; j++)
                g_Wbig[(size_t)l * UD_ + D_ + h * D_ + d0 + dg * 8 + j] = acc[i][j] * inv;
    }
}

__global__ void k_mtsum(const float* __restrict__ mt) {
    int d = threadIdx.x;
    float s = 0.f;
    for (int q = 0; q < S_; q++) s += mt[q * D_ + d];
    g_mtsum[d] = s;
}

__global__ void k_lvec(const float* __restrict__ predw, const float* __restrict__ predb,
                       const float* __restrict__ ipb, const float* __restrict__ outb) {
    int l = threadIdx.x;
    if (l >= L_) return;
    const float inv = 1.f / (float)S_;
    const float* bv = ipb + 2 * D_;
    float cb = 0.f;
    for (int i = 0; i < D_; i++) cb += bv[i] * g_Wcp[l * D_ + i];
    for (int m = 0; m < D_; m++) cb += outb[m] * predw[l * D_ + m];
    g_cbias[l] = cb * inv;
    float lm = 0.f;
    for (int d = 0; d < D_; d++) lm += g_mtsum[d] * predw[l * D_ + d];
    g_logit_mt[l] = lm * inv + predb[l];
}

// ---------------- compaction: count + prefix scan in one kernel --------------
__global__ void k_scan(const int* __restrict__ ex) {
    __shared__ int sm[1024];
    int tid = threadIdx.x;
    int v[4];
    int loc = 0;
    #pragma unroll
    for (int i = 0; i < 4; i++) {
        int b = tid * 4 + i;
        int n = 0;
        for (int s = 0; s < S_; s++) n += (ex[b * S_ + s] != 0);
        g_nexist[b] = n;
        v[i] = n; loc += n;
    }
    sm[tid] = loc;
    __syncthreads();
    for (int off = 1; off < 1024; off <<= 1) {
        int add = (tid >= off) ? sm[tid - off] : 0;
        __syncthreads();
        sm[tid] += add;
        __syncthreads();
    }
    int run = sm[tid] - loc;
    #pragma unroll
    for (int i = 0; i < 4; i++) { g_start[tid * 4 + i] = run; run += v[i]; }
    if (tid == 1023) g_start[B_] = run;
}

__global__ void k_rowidx(const int* __restrict__ ex) {
    int b = blockIdx.x * blockDim.x + threadIdx.x;
    if (b >= B_) return;
    int p = g_start[b];
    for (int s = 0; s < S_; s++)
        if (ex[b * S_ + s] != 0) g_rowidx[p++] = b * S_ + s;
}

// ---------------- main scores GEMM: Y[r,c] = cls[rowidx[r],:] . P[c,:] --------
// BM=128, BN=192, BK=16, 256 threads, 8x12 per thread via FFMA2.
__global__ void __launch_bounds__(256) k_gemm(const float* __restrict__ cls, int vec_ok) {
    const int total = g_start[B_];
    const int m0 = blockIdx.x * 128;
    if (m0 >= total) return;
    __shared__ __align__(16) float2 As2[16][128];
    __shared__ __align__(16) float  Bs[16][192];
    __shared__ int rsrc[128];
    int tid = threadIdx.x;
    if (tid < 128) {
        int r = m0 + tid;
        rsrc[tid] = (r < total) ? g_rowidx[r] : -1;
    }
    __syncthreads();

    int tx = tid & 15, ty = tid >> 4;
    unsigned long long acc[8][6];
    #pragma unroll
    for (int i = 0; i < 8; i++)
        #pragma unroll
        for (int j = 0; j < 6; j++) acc[i][j] = 0ull;

    float4 pa[2], pb[3];

    auto load_tile = [&](int k0) {
        #pragma unroll
        for (int i = 0; i < 2; i++) {
            int idx = i * 256 + tid;
            int row = idx >> 2, c0 = (idx & 3) * 4;
            int src = rsrc[row];
            float4 v = make_float4(0.f, 0.f, 0.f, 0.f);
            if (src >= 0) {
                const float* sp = cls + (size_t)src * D_ + k0 + c0;
                if (vec_ok) v = *(const float4*)sp;
                else { v.x = sp[0]; v.y = sp[1]; v.z = sp[2]; v.w = sp[3]; }
            }
            pa[i] = v;
        }
        #pragma unroll
        for (int i = 0; i < 3; i++) {
            int idx = i * 256 + tid;
            int n = idx >> 2, c4 = idx & 3;
            pb[i] = *(const float4*)(g_P + (size_t)n * D_ + k0 + c4 * 4);
        }
    };
    auto store_tile = [&]() {
        #pragma unroll
        for (int i = 0; i < 2; i++) {
            int idx = i * 256 + tid;
            int row = idx >> 2, c0 = (idx & 3) * 4;
            float4 v = pa[i];
            As2[c0 + 0][row] = make_float2(v.x, v.x);
            As2[c0 + 1][row] = make_float2(v.y, v.y);
            As2[c0 + 2][row] = make_float2(v.z, v.z);
            As2[c0 + 3][row] = make_float2(v.w, v.w);
        }
        #pragma unroll
        for (int i = 0; i < 3; i++) {
            int idx = i * 256 + tid;
            int n = idx >> 2, c4 = idx & 3;
            float4 v = pb[i];
            Bs[c4 * 4 + 0][n] = v.x;
            Bs[c4 * 4 + 1][n] = v.y;
            Bs[c4 * 4 + 2][n] = v.z;
            Bs[c4 * 4 + 3][n] = v.w;
        }
    };

    load_tile(0);
    for (int k0 = 0; k0 < D_; k0 += 16) {
        store_tile();
        __syncthreads();
        if (k0 + 16 < D_) load_tile(k0 + 16);
        #pragma unroll
        for (int k = 0; k < 16; k++) {
            const ulonglong2* ap = (const ulonglong2*)&As2[k][ty * 8];
            ulonglong2 A0 = ap[0], A1 = ap[1], A2 = ap[2], A3 = ap[3];
            unsigned long long a2[8] = {A0.x, A0.y, A1.x, A1.y, A2.x, A2.y, A3.x, A3.y};
            const ulonglong2* bp = (const ulonglong2*)&Bs[k][tx * 12];
            ulonglong2 B0 = bp[0], B1 = bp[1], B2 = bp[2];
            unsigned long long b2[6] = {B0.x, B0.y, B1.x, B1.y, B2.x, B2.y};
            #pragma unroll
            for (int i = 0; i < 8; i++)
                #pragma unroll
                for (int j = 0; j < 6; j++)
                    acc[i][j] = ffma2(a2[i], b2[j], acc[i][j]);
        }
        __syncthreads();
    }
    #pragma unroll
    for (int i = 0; i < 8; i++) {
        int r = m0 + ty * 8 + i;
        if (r < total) {
            unsigned long long* yp = (unsigned long long*)(g_Y + (size_t)r * CP_ + tx * 12);
            ulonglong2 s0; s0.x = acc[i][0]; s0.y = acc[i][1];
            ulonglong2 s1; s1.x = acc[i][2]; s1.y = acc[i][3];
            ulonglong2 s2; s2.x = acc[i][4]; s2.y = acc[i][5];
            ((ulonglong2*)yp)[0] = s0;
            ((ulonglong2*)yp)[1] = s1;
            ((ulonglong2*)yp)[2] = s2;
        }
    }
}

// ---------------- per-sample attention + reduction ----------------------------
__global__ void __launch_bounds__(128) k_attn(const float* __restrict__ cls,
                                              const int* __restrict__ ex) {
    int b = blockIdx.x;
    int tid = threadIdx.x;
    __shared__ float Ys[S_][C_];
    __shared__ float shk[H_][S_];
    __shared__ float qbs[C_];
    __shared__ int ke[S_], qm[S_];
    __shared__ int info[3];
    if (tid == 0) {
        int ne = 0, nm = 0;
        for (int s = 0; s < S_; s++) {
            if (ex[b * S_ + s] != 0) ke[ne++] = s; else qm[nm++] = s;
        }
        info[0] = ne; info[1] = nm; info[2] = g_start[b];
    }
    for (int i = tid; i < C_; i += 128) qbs[i] = g_qb[i];
    for (int i = tid; i < H_ * S_; i += 128) (&shk[0][0])[i] = 0.f;
    __syncthreads();
    int ne = info[0], nm = info[1], st = info[2];
    if (ne == 0) {
        for (int i = tid; i < UD_; i += 128) g_U[(size_t)b * UD_ + i] = 0.f;
        return;
    }
    for (int i = tid; i < ne * C_; i += 128) {
        int k = i / C_, c = i % C_;
        Ys[k][c] = g_Y[(size_t)(st + k) * CP_ + c];
    }
    __syncthreads();
    const float scale = rsqrtf((float)HD_);
    // softmax per (head, missing query); each c owned by exactly one thread,
    // so Ys[:,c] is reused as scratch across the three passes.
    for (int p = tid; p < H_ * nm; p += 128) {
        int h = p / nm, qi = p % nm;
        int c = h * S_ + qm[qi];
        float qb = qbs[c];
        float mx = -3.0e38f;
        for (int k = 0; k < ne; k++) {
            float t = scale * (Ys[k][c] + qb);
            Ys[k][c] = t;
            mx = fmaxf(mx, t);
        }
        float sum = 0.f;
        for (int k = 0; k < ne; k++) {
            float e = expf(Ys[k][c] - mx);
            Ys[k][c] = e;
            sum += e;
        }
        float inv = 1.f / sum;
        for (int k = 0; k < ne; k++)
            atomicAdd(&shk[h][k], Ys[k][c] * inv);
    }
    __syncthreads();
    for (int ch = 0; ch < D_ / 128; ch++) {
        int d = ch * 128 + tid;
        float cs = 0.f;
        float au[H_];
        #pragma unroll
        for (int h = 0; h < H_; h++) au[h] = 0.f;
        for (int k = 0; k < ne; k++) {
            float c = cls[((size_t)b * S_ + ke[k]) * D_ + d];
            cs += c;
            #pragma unroll
            for (int h = 0; h < H_; h++) au[h] += shk[h][k] * c;
        }
        size_t ub = (size_t)b * UD_;
        g_U[ub + d] = cs;
        #pragma unroll
        for (int h = 0; h < H_; h++) g_U[ub + D_ + (size_t)h * D_ + d] = au[h];
    }
}

// ---------------- final logits GEMM + epilogue --------------------------------
__global__ void k_zero(float* out) {
    int i = blockIdx.x * blockDim.x + threadIdx.x;
    if (i < B_ * L_) out[i] = 0.f;
}

#define KSPLIT 8
#define KSLICE (UD_ / KSPLIT)   // 864
__global__ void __launch_bounds__(256) k_final(float* __restrict__ out) {
    int m0 = blockIdx.x * 128;
    int koff0 = blockIdx.y * KSLICE;
    __shared__ __align__(16) float2 As2[16][128];
    __shared__ __align__(16) float  Bs[16][64];
    int tid = threadIdx.x;
    int tx = tid & 7, ty = tid >> 3;
    unsigned long long acc[4][4];
    #pragma unroll
    for (int i = 0; i < 4; i++)
        #pragma unroll
        for (int j = 0; j < 4; j++) acc[i][j] = 0ull;

    float4 fa[2], fb;

    auto load_tile = [&](int kb) {
        #pragma unroll
        for (int i = 0; i < 2; i++) {
            int idx = i * 256 + tid;
            int row = idx >> 2, c0 = (idx & 3) * 4;
            fa[i] = *(const float4*)(g_U + (size_t)(m0 + row) * UD_ + kb + c0);
        }
        {
            int n = tid >> 2, c0 = (tid & 3) * 4;
            float4 v = make_float4(0.f, 0.f, 0.f, 0.f);
            if (n < L_) v = *(const float4*)(g_Wbig + (size_t)n * UD_ + kb + c0);
            fb = v;
        }
    };
    auto store_tile = [&]() {
        #pragma unroll
        for (int i = 0; i < 2; i++) {
            int idx = i * 256 + tid;
            int row = idx >> 2, c0 = (idx & 3) * 4;
            float4 v = fa[i];
            As2[c0 + 0][row] = make_float2(v.x, v.x);
            As2[c0 + 1][row] = make_float2(v.y, v.y);
            As2[c0 + 2][row] = make_float2(v.z, v.z);
            As2[c0 + 3][row] = make_float2(v.w, v.w);
        }
        {
            int n = tid >> 2, c0 = (tid & 3) * 4;
            float4 v = fb;
            Bs[c0 + 0][n] = v.x;
            Bs[c0 + 1][n] = v.y;
            Bs[c0 + 2][n] = v.z;
            Bs[c0 + 3][n] = v.w;
        }
    };

    load_tile(koff0);
    for (int k0 = 0; k0 < KSLICE; k0 += 16) {
        store_tile();
        __syncthreads();
        if (k0 + 16 < KSLICE) load_tile(koff0 + k0 + 16);
        #pragma unroll
        for (int k = 0; k < 16; k++) {
            const ulonglong2* ap = (const ulonglong2*)&As2[k][ty * 4];
            ulonglong2 A0 = ap[0], A1 = ap[1];
            unsigned long long a2[4] = {A0.x, A0.y, A1.x, A1.y};
            const ulonglong2* bp = (const ulonglong2*)&Bs[k][tx * 8];
            ulonglong2 B0 = bp[0], B1 = bp[1];
            unsigned long long b2[4] = {B0.x, B0.y, B1.x, B1.y};
            #pragma unroll
            for (int i = 0; i < 4; i++)
                #pragma unroll
                for (int j = 0; j < 4; j++)
                    acc[i][j] = ffma2(a2[i], b2[j], acc[i][j]);
        }
        __syncthreads();
    }
    #pragma unroll
    for (int i = 0; i < 4; i++) {
        int m = m0 + ty * 4 + i;
        #pragma unroll
        for (int j = 0; j < 4; j++) {
            int n = tx * 8 + 2 * j;
            if (n < L_)     atomicAdd(&out[(size_t)m * L_ + n],     f2_lo(acc[i][j]));
            if (n + 1 < L_) atomicAdd(&out[(size_t)m * L_ + n + 1], f2_hi(acc[i][j]));
        }
    }
}

__global__ void k_epi(float* __restrict__ out, const float* __restrict__ predb) {
    int b = blockIdx.x;
    int l = threadIdx.x;
    if (l >= L_) return;
    int ne = g_nexist[b];
    if (ne == 0) out[(size_t)b * L_ + l] = g_logit_mt[l];
    else out[(size_t)b * L_ + l] += (float)(S_ - ne) * g_cbias[l] + predb[l];
}

// ---------------- launch -------------------------------------------------------
extern "C" void kernel_launch(void* const* d_in, const int* in_sizes, int n_in,
                              void* d_out, int out_size) {
    const float *cls = 0, *mt = 0, *ipw = 0, *ipb = 0, *outw = 0, *outb = 0,
                *predw = 0, *predb = 0;
    const int* ex = 0;
    for (int i = 0; i < n_in; i++) {
        switch (in_sizes[i]) {
            case B_ * S_ * D_:  cls   = (const float*)d_in[i]; break;
            case S_ * D_:       mt    = (const float*)d_in[i]; break;
            case 3 * D_ * D_:   ipw   = (const float*)d_in[i]; break;
            case 3 * D_:        ipb   = (const float*)d_in[i]; break;
            case D_ * D_:       outw  = (const float*)d_in[i]; break;
            case D_:            outb  = (const float*)d_in[i]; break;
            case L_ * D_:       predw = (const float*)d_in[i]; break;
            case L_:            predb = (const float*)d_in[i]; break;
            case B_ * S_:       ex    = (const int*)d_in[i];   break;
        }
    }
    if (!cls || !mt || !ipw || !ipb || !outw || !outb || !predw || !predb || !ex) {
        cls   = (const float*)d_in[0];
        mt    = (const float*)d_in[1];
        ipw   = (const float*)d_in[2];
        ipb   = (const float*)d_in[3];
        outw  = (const float*)d_in[4];
        outb  = (const float*)d_in[5];
        predw = (const float*)d_in[6];
        predb = (const float*)d_in[7];
        ex    = (const int*)d_in[8];
    }
    float* out = (float*)d_out;
    int vec_cls = (((uintptr_t)cls & 15) == 0) ? 1 : 0;
    int vec_ipw = (((uintptr_t)ipw & 15) == 0) ? 1 : 0;

    // Launch order matters: ncu profiles launch #6 (-s 5 -c 1) -> k_gemm.
    k_qmiss<<<dim3(6, S_), 128>>>(mt, ipw, ipb, vec_ipw);        // 1
    k_P<<<dim3(3, CP_), 256>>>(ipw, ipb);                        // 2 (incl. pad)
    k_scan<<<1, 1024>>>(ex);                                     // 3 (count+scan)
    k_rowidx<<<B_ / 256, 256>>>(ex);                             // 4
    k_wcpzero<<<150, 256>>>();                                   // 5
    k_gemm<<<(B_ * S_) / 128, 256>>>(cls, vec_cls);              // 6  <- profiled
    k_wcp<<<dim3(6, 8), 256>>>(predw, outw);                     // 7
    k_wbig<<<dim3(6, 9), 256>>>(predw, ipw);                     // 8
    k_mtsum<<<1, D_>>>(mt);                                      // 9
    k_lvec<<<1, 64>>>(predw, predb, ipb, outb);                  // 10
    k_attn<<<B_, 128>>>(cls, ex);                                // 11
    k_zero<<<(B_ * L_ + 255) / 256, 256>>>(out);                 // 12
    k_final<<<dim3(B_ / 128, KSPLIT), 256>>>(out);               // 13
    k_epi<<<B_, 64>>>(out, predb);                               // 14
}